// round 1
// baseline (speedup 1.0000x reference)
#include <cuda_runtime.h>
#include <math.h>

#define Bv 64
#define Sv 256
#define Ev 300
#define Hv 300
#define H2 600
#define G4 1200
#define Rv 512
#define NRELv 46
#define RELDv 50

// ---------------- device scratch (no allocations allowed) ----------------
__device__ float d_text[Bv * Sv * Ev];          // [b][s][e]
__device__ float d_Xg[2 * Sv * Bv * G4];        // [dir][s][b][1200] pre-activation input gates
__device__ float d_hseq[2 * Sv * Hv * Bv];      // [dir][t][u][b]
__device__ float d_cst[2 * Hv * Bv];            // [dir][u][b]
__device__ float d_to[Bv * Sv * H2];            // text_out [b][s][600]
__device__ float d_pw[Bv * Sv * H2];            // pos-weighted input to GCN gemm
__device__ float d_hid[Bv * Sv * H2];           // hidden = pw @ gcW
__device__ float d_x1[Bv * Sv * H2];            // gcn output (layer1 then layer2)
__device__ float d_V[NRELv * G4];               // bil_W @ rel_embed^T
__device__ float d_score[Bv * Rv];
__device__ float d_pwv[Bv * Sv];
__device__ float d_xsum[Bv * H2];
__device__ float d_attsc[Bv * Sv];
__device__ float d_alpha[Bv * Sv];
__device__ float d_ov[Bv * H2];
__device__ int d_tlen[Bv], d_alen[Bv], d_llen[Bv];

// ---------------- lengths ----------------
__global__ void len_kernel(const int* __restrict__ ti, const int* __restrict__ ai,
                           const int* __restrict__ li) {
    int b = threadIdx.x;
    if (b >= Bv) return;
    int t = 0;
    for (int s = 0; s < Sv; s++) t += (ti[b * Sv + s] != 0);
    int a = 0;
    for (int s = 0; s < 4; s++) a += (ai[b * 4 + s] != 0);
    int l = 0;
    for (int s = 0; s < 64; s++) l += (li[b * 64 + s] != 0);
    d_tlen[b] = t;
    d_alen[b] = a;
    d_llen[b] = l;
}

// ---------------- embedding gather ----------------
__global__ void embed_kernel(const int* __restrict__ idx, const float* __restrict__ emb) {
    int i = blockIdx.x * 256 + threadIdx.x;
    if (i >= Bv * Sv * Ev) return;
    int e = i % Ev;
    int m = i / Ev;
    d_text[i] = emb[idx[m] * Ev + e];
}

// ---------------- SGEMM: C[M,N] = A[M,K] * B (+bias) ----------------
// BT=true : B is [N,K] row-major (multiply by B^T)
// BT=false: B is [K,N] row-major
// EPI 0: C[m*N+n] = acc (+bias if non-null)
// EPI 1: (Xall) row m = b*Sv + s -> C[(s*Bv+b)*G4 + n] = acc + bias[n]
template <int EPI, bool BT>
__global__ void sgemm_kernel(const float* __restrict__ A, const float* __restrict__ Bm,
                             const float* __restrict__ bias, float* __restrict__ C,
                             int M, int N, int K) {
    __shared__ float As[8 * 128];
    __shared__ float Bs[8 * 64];
    const int m0 = blockIdx.y * 128;
    const int n0 = blockIdx.x * 64;
    const int tid = threadIdx.x;
    const int ty = tid >> 4;   // 0..15 -> m
    const int tx = tid & 15;   // 0..15 -> n

    float acc[8][4];
#pragma unroll
    for (int r = 0; r < 8; r++)
#pragma unroll
        for (int c = 0; c < 4; c++) acc[r][c] = 0.f;

    const int a_m = tid >> 1;          // 0..127
    const int a_k = (tid & 1) * 4;     // 0 or 4

    for (int k0 = 0; k0 < K; k0 += 8) {
        // load A tile (128 x 8), transpose to As[k][m]
        float4 av = make_float4(0.f, 0.f, 0.f, 0.f);
        if (k0 + a_k < K)  // K % 4 == 0 in all our uses
            av = *(const float4*)&A[(m0 + a_m) * K + k0 + a_k];
        As[(a_k + 0) * 128 + a_m] = av.x;
        As[(a_k + 1) * 128 + a_m] = av.y;
        As[(a_k + 2) * 128 + a_m] = av.z;
        As[(a_k + 3) * 128 + a_m] = av.w;

        // load B tile into Bs[k][n]
        if (BT) {
            int n_l = tid >> 2;            // 0..63
            int kk = (tid & 3) * 2;        // 0,2,4,6
            int row = n0 + n_l;
#pragma unroll
            for (int d2 = 0; d2 < 2; d2++) {
                int k = k0 + kk + d2;
                Bs[(kk + d2) * 64 + n_l] = (row < N && k < K) ? Bm[row * K + k] : 0.f;
            }
        } else {
            int kk = tid >> 5;             // 0..7
            int n_l = (tid & 31) * 2;      // 0..62
#pragma unroll
            for (int d2 = 0; d2 < 2; d2++) {
                int n = n_l + d2;
                Bs[kk * 64 + n] = (k0 + kk < K && n0 + n < N) ? Bm[(k0 + kk) * N + n0 + n] : 0.f;
            }
        }
        __syncthreads();

#pragma unroll
        for (int kk = 0; kk < 8; kk++) {
            float4 a0 = *(float4*)&As[kk * 128 + ty * 8];
            float4 a1 = *(float4*)&As[kk * 128 + ty * 8 + 4];
            float4 bv = *(float4*)&Bs[kk * 64 + tx * 4];
            float ar[8] = {a0.x, a0.y, a0.z, a0.w, a1.x, a1.y, a1.z, a1.w};
            float bc[4] = {bv.x, bv.y, bv.z, bv.w};
#pragma unroll
            for (int r = 0; r < 8; r++)
#pragma unroll
                for (int c = 0; c < 4; c++) acc[r][c] += ar[r] * bc[c];
        }
        __syncthreads();
    }

#pragma unroll
    for (int r = 0; r < 8; r++) {
        int row = m0 + ty * 8 + r;
#pragma unroll
        for (int c = 0; c < 4; c++) {
            int col = n0 + tx * 4 + c;
            if (col < N) {
                float v = acc[r][c];
                if (EPI == 0) {
                    if (bias) v += bias[col];
                    C[row * N + col] = v;
                } else {
                    int bb = row >> 8;   // row / 256
                    int ss = row & 255;  // row % 256
                    C[(ss * Bv + bb) * G4 + col] = v + bias[col];
                }
            }
        }
    }
}

// ---------------- LSTM recurrent step (both directions), one launch/step ----------------
// grid: (75, 2)  block: 256  — block covers 4 hidden units x 4 gates x 64 batches
__global__ void lstm_step(int step, const float* __restrict__ Wfh,
                          const float* __restrict__ Wbh) {
    __shared__ float sW[300 * 16];
    __shared__ float sG[16 * 64];
    const int d = blockIdx.y;
    const int ub = blockIdx.x * 4;
    const float* __restrict__ W = (d == 0) ? Wfh : Wbh;
    const int tid = threadIdx.x;

    // stage 16 W_hh rows (k-major) into smem
    for (int idx = tid; idx < 16 * 300; idx += 256) {
        int jl = idx / 300, k = idx % 300;
        int j = (jl >> 2) * 300 + ub + (jl & 3);
        sW[k * 16 + jl] = W[j * 300 + k];
    }
    __syncthreads();

    const int t_x = (d == 0) ? step : (Sv - 1 - step);
    const int jl = tid & 15;
    const int b0 = (tid >> 4) * 4;
    const int j = (jl >> 2) * 300 + ub + (jl & 3);
    const float* __restrict__ Xb = d_Xg + (d * Sv + t_x) * Bv * G4;

    float acc0 = Xb[(b0 + 0) * G4 + j];
    float acc1 = Xb[(b0 + 1) * G4 + j];
    float acc2 = Xb[(b0 + 2) * G4 + j];
    float acc3 = Xb[(b0 + 3) * G4 + j];

    if (step > 0) {
        const int t_hp = (d == 0) ? (step - 1) : (Sv - step);
        const float4* __restrict__ Hp =
            (const float4*)(d_hseq + (d * Sv + t_hp) * Hv * Bv);
        const int hq = b0 >> 2;
#pragma unroll 4
        for (int k = 0; k < 300; k++) {
            float w = sW[k * 16 + jl];
            float4 h4 = __ldg(&Hp[k * 16 + hq]);
            acc0 += w * h4.x;
            acc1 += w * h4.y;
            acc2 += w * h4.z;
            acc3 += w * h4.w;
        }
    }
    sG[jl * 64 + b0 + 0] = acc0;
    sG[jl * 64 + b0 + 1] = acc1;
    sG[jl * 64 + b0 + 2] = acc2;
    sG[jl * 64 + b0 + 3] = acc3;
    __syncthreads();

    // finalize: 4 units x 64 batches
    const int u_l = tid >> 6;
    const int b = tid & 63;
    float gi = sG[(0 * 4 + u_l) * 64 + b];
    float gf = sG[(1 * 4 + u_l) * 64 + b];
    float gg = sG[(2 * 4 + u_l) * 64 + b];
    float go = sG[(3 * 4 + u_l) * 64 + b];
    const int u = ub + u_l;
    float cp = (step == 0) ? 0.f : d_cst[(d * Hv + u) * 64 + b];
    float si = 1.f / (1.f + expf(-gi));
    float sf = 1.f / (1.f + expf(-gf));
    float so = 1.f / (1.f + expf(-go));
    float c = sf * cp + si * tanhf(gg);
    d_cst[(d * Hv + u) * 64 + b] = c;
    float h = so * tanhf(c);
    d_hseq[((d * Sv + t_x) * Hv + u) * 64 + b] = h;
}

// ---------------- assemble text_out [b][s][600] ----------------
__global__ void assemble_to() {
    int i = blockIdx.x * 256 + threadIdx.x;
    if (i >= Bv * Sv * H2) return;
    int h = i % H2;
    int bs = i / H2;
    int s = bs % Sv;
    int b = bs / Sv;
    int dsel = (h >= Hv) ? 1 : 0;
    int u = h - dsel * Hv;
    d_to[i] = d_hseq[((dsel * Sv + s) * Hv + u) * 64 + b];
}

// ---------------- V = bil_W @ rel_embed^T ----------------
__global__ void vprep(const float* __restrict__ bw, const float* __restrict__ re) {
    int r = blockIdx.x;
    for (int i = threadIdx.x; i < G4; i += 256) {
        float a = 0.f;
#pragma unroll
        for (int jj = 0; jj < RELDv; jj++) a += bw[i * RELDv + jj] * re[r * RELDv + jj];
        d_V[r * G4 + i] = a;
    }
}

// ---------------- relation scores (warp per (b,r)) ----------------
__global__ void relscore(const int* __restrict__ head, const int* __restrict__ behead,
                         const int* __restrict__ rel, const float* __restrict__ bilb) {
    int g = blockIdx.x * 8 + (threadIdx.x >> 5);
    int lane = threadIdx.x & 31;
    if (g >= Bv * Rv) return;
    int b = g / Rv;
    int rr = rel[g];
    float dotv = 0.f;
    if (rr != 0) {
        int h1 = head[g], h2 = behead[g];
        const float* __restrict__ n1 = d_to + (b * Sv + h1) * H2;
        const float* __restrict__ n2 = d_to + (b * Sv + h2) * H2;
        const float* __restrict__ V = d_V + rr * G4;
        for (int i = lane; i < H2; i += 32) dotv += n1[i] * V[i] + n2[i] * V[H2 + i];
    }
#pragma unroll
    for (int o = 16; o; o >>= 1) dotv += __shfl_down_sync(0xffffffffu, dotv, o);
    if (lane == 0) d_score[g] = 1.f / (1.f + expf(-(dotv + bilb[0])));
}

// ---------------- position weights ----------------
__global__ void pwv_kernel() {
    int b = blockIdx.x;
    int s = threadIdx.x;
    float tl = (float)d_tlen[b];
    float al = (float)d_alen[b];
    float l0 = (float)d_llen[b];
    float l1 = l0 + al - 1.f;
    float ctx = tl - al;
    float jf = (float)s;
    float w;
    if (jf < l0) w = 1.f - (l0 - jf) / ctx;
    else if (jf <= l1) w = 0.f;
    else if (jf < tl) w = 1.f - (jf - l1) / ctx;
    else w = 0.f;
    d_pwv[b * Sv + s] = w;
}

__global__ void pw_apply(const float* __restrict__ src) {
    int i = blockIdx.x * 256 + threadIdx.x;
    if (i >= Bv * Sv * H2) return;
    d_pw[i] = src[i] * d_pwv[i / H2];
}

// ---------------- sparse GCN apply: out = relu(adj@hidden/den + bias) ----------------
__global__ void gcn_apply(const int* __restrict__ head, const int* __restrict__ behead,
                          const float* __restrict__ bias, float* __restrict__ out) {
    int bs = blockIdx.x;
    int b = bs >> 8;
    int s1 = bs & 255;
    const int* hd = head + b * Rv;
    int L = 0, Rr = Rv;
    while (L < Rr) { int m = (L + Rr) >> 1; if (hd[m] < s1) L = m + 1; else Rr = m; }
    int lo = L;
    Rr = Rv;
    while (L < Rr) { int m = (L + Rr) >> 1; if (hd[m] <= s1) L = m + 1; else Rr = m; }
    int hi = L;
    float den = 1.f;
    for (int r = lo; r < hi; r++) den += d_score[b * Rv + r];
    float inv = 1.f / den;
    for (int h = threadIdx.x; h < H2; h += 128) {
        float a = 0.f;
        for (int r = lo; r < hi; r++)
            a += d_score[b * Rv + r] * d_hid[(b * Sv + behead[b * Rv + r]) * H2 + h];
        float v = a * inv + bias[h];
        out[(b * Sv + s1) * H2 + h] = fmaxf(v, 0.f);
    }
}

// ---------------- attention ----------------
__global__ void xsum_kernel(const float* __restrict__ x) {
    int b = blockIdx.x;
    int h = threadIdx.x;
    if (h >= H2) return;
    int l0 = d_llen[b];
    int l1 = l0 + d_alen[b] - 1;
    if (l1 > Sv - 1) l1 = Sv - 1;
    float a = 0.f;
    for (int s = l0; s <= l1; s++) a += x[(b * Sv + s) * H2 + h];
    d_xsum[b * H2 + h] = a;
}

__global__ void attscore() {
    int g = blockIdx.x * 8 + (threadIdx.x >> 5);
    int lane = threadIdx.x & 31;
    if (g >= Bv * Sv) return;
    int b = g >> 8;
    float a = 0.f;
    for (int i = lane; i < H2; i += 32) a += d_xsum[b * H2 + i] * d_to[g * H2 + i];
#pragma unroll
    for (int o = 16; o; o >>= 1) a += __shfl_down_sync(0xffffffffu, a, o);
    if (lane == 0) d_attsc[g] = a;
}

__global__ void softmax_kernel() {
    __shared__ float red[256];
    int b = blockIdx.x;
    int tid = threadIdx.x;
    float v = d_attsc[b * Sv + tid];
    red[tid] = v;
    __syncthreads();
    for (int o = 128; o; o >>= 1) {
        if (tid < o) red[tid] = fmaxf(red[tid], red[tid + o]);
        __syncthreads();
    }
    float smax = red[0];
    __syncthreads();
    float e = expf(v - smax);
    red[tid] = e;
    __syncthreads();
    for (int o = 128; o; o >>= 1) {
        if (tid < o) red[tid] += red[tid + o];
        __syncthreads();
    }
    d_alpha[b * Sv + tid] = e / red[0];
}

__global__ void outvec_kernel() {
    int b = blockIdx.x;
    int h = threadIdx.x;
    if (h >= H2) return;
    float a = 0.f;
    for (int s = 0; s < Sv; s++) a += d_alpha[b * Sv + s] * d_to[(b * Sv + s) * H2 + h];
    d_ov[b * H2 + h] = a;
}

__global__ void final_fc(const float* __restrict__ fcW, const float* __restrict__ fcb,
                         float* __restrict__ out) {
    int b = blockIdx.x;
    int p = threadIdx.x >> 5;
    int lane = threadIdx.x & 31;
    if (p >= 3) return;
    float a = 0.f;
    for (int h = lane; h < H2; h += 32) a += d_ov[b * H2 + h] * fcW[h * 3 + p];
#pragma unroll
    for (int o = 16; o; o >>= 1) a += __shfl_down_sync(0xffffffffu, a, o);
    if (lane == 0) out[b * 3 + p] = a + fcb[p];
}

// ---------------- launch ----------------
extern "C" void kernel_launch(void* const* d_in, const int* in_sizes, int n_in,
                              void* d_out, int out_size) {
    const int* text_indices = (const int*)d_in[0];
    const int* aspect_indices = (const int*)d_in[1];
    const int* left_indices = (const int*)d_in[2];
    // d_in[3] = adj (dense) — unused: its nonzeros are exactly (head, behead)
    const int* head_vector = (const int*)d_in[4];
    const int* behead_vector = (const int*)d_in[5];
    const int* relation_vector = (const int*)d_in[6];
    const float* embed_table = (const float*)d_in[7];
    const float* rel_embed = (const float*)d_in[8];
    const float* Wf_ih = (const float*)d_in[9];
    const float* Wf_hh = (const float*)d_in[10];
    const float* bf = (const float*)d_in[11];
    const float* Wb_ih = (const float*)d_in[12];
    const float* Wb_hh = (const float*)d_in[13];
    const float* bb = (const float*)d_in[14];
    const float* bil_W = (const float*)d_in[15];
    const float* bil_b = (const float*)d_in[16];
    const float* gc1_W = (const float*)d_in[17];
    const float* gc1_b = (const float*)d_in[18];
    const float* gc2_W = (const float*)d_in[19];
    const float* gc2_b = (const float*)d_in[20];
    const float* fc_W = (const float*)d_in[21];
    const float* fc_b = (const float*)d_in[22];
    float* out = (float*)d_out;

    float* p_text;  cudaGetSymbolAddress((void**)&p_text, d_text);
    float* p_Xg;    cudaGetSymbolAddress((void**)&p_Xg, d_Xg);
    float* p_to;    cudaGetSymbolAddress((void**)&p_to, d_to);
    float* p_pw;    cudaGetSymbolAddress((void**)&p_pw, d_pw);
    float* p_hid;   cudaGetSymbolAddress((void**)&p_hid, d_hid);
    float* p_x1;    cudaGetSymbolAddress((void**)&p_x1, d_x1);

    len_kernel<<<1, 64>>>(text_indices, aspect_indices, left_indices);
    embed_kernel<<<(Bv * Sv * Ev + 255) / 256, 256>>>(text_indices, embed_table);

    // input-side gate GEMMs: [16384,300] x [300,1200]^T (+bias), scattered to [s][b][j]
    {
        dim3 g((G4 + 63) / 64, (Bv * Sv) / 128);
        sgemm_kernel<1, true><<<g, 256>>>(p_text, Wf_ih, bf, p_Xg, Bv * Sv, G4, Ev);
        sgemm_kernel<1, true><<<g, 256>>>(p_text, Wb_ih, bb, p_Xg + Sv * Bv * G4,
                                          Bv * Sv, G4, Ev);
    }

    // recurrence: 256 sequential steps, fwd+bwd fused per launch
    for (int step = 0; step < Sv; step++)
        lstm_step<<<dim3(75, 2), 256>>>(step, Wf_hh, Wb_hh);

    assemble_to<<<(Bv * Sv * H2 + 255) / 256, 256>>>();

    // relation scoring
    vprep<<<NRELv, 256>>>(bil_W, rel_embed);
    relscore<<<(Bv * Rv) / 8, 256>>>(head_vector, behead_vector, relation_vector, bil_b);

    pwv_kernel<<<Bv, Sv>>>();

    // GCN layer 1
    pw_apply<<<(Bv * Sv * H2 + 255) / 256, 256>>>(p_to);
    {
        dim3 g((H2 + 63) / 64, (Bv * Sv) / 128);
        sgemm_kernel<0, false><<<g, 256>>>(p_pw, gc1_W, nullptr, p_hid, Bv * Sv, H2, H2);
    }
    gcn_apply<<<Bv * Sv, 128>>>(head_vector, behead_vector, gc1_b, p_x1);

    // GCN layer 2
    pw_apply<<<(Bv * Sv * H2 + 255) / 256, 256>>>(p_x1);
    {
        dim3 g((H2 + 63) / 64, (Bv * Sv) / 128);
        sgemm_kernel<0, false><<<g, 256>>>(p_pw, gc2_W, nullptr, p_hid, Bv * Sv, H2, H2);
    }
    gcn_apply<<<Bv * Sv, 128>>>(head_vector, behead_vector, gc2_b, p_x1);

    // attention (alpha_mat collapses: sum over axis 1 first)
    xsum_kernel<<<Bv, 640>>>(p_x1);
    attscore<<<(Bv * Sv) / 8, 256>>>();
    softmax_kernel<<<Bv, 256>>>();
    outvec_kernel<<<Bv, 640>>>();
    final_fc<<<Bv, 96>>>(fc_W, fc_b, out);

    (void)in_sizes; (void)n_in; (void)out_size;
}

// round 2
// speedup vs baseline: 1.1412x; 1.1412x over previous
#include <cuda_runtime.h>
#include <math.h>

#define Bv 64
#define Sv 256
#define Ev 300
#define Hv 300
#define H2 600
#define G4 1200
#define Rv 512
#define NRELv 46
#define RELDv 50

#define LSTM_BLOCKS_PER_DIR 60   // 5 units per block
#define LSTM_THREADS 320         // 20 rows x 16 batch-quads

// ---------------- device scratch (no allocations allowed) ----------------
__device__ float d_text[Bv * Sv * Ev];          // [b][s][e]
__device__ float d_Xg[2 * Sv * Bv * G4];        // [dir][s][b][1200] pre-activation input gates
__device__ float d_hseq[2 * Sv * Hv * Bv];      // [dir][t][u][b]
__device__ float d_to[Bv * Sv * H2];            // text_out [b][s][600]
__device__ float d_pw[Bv * Sv * H2];            // pos-weighted input to GCN gemm
__device__ float d_hid[Bv * Sv * H2];           // hidden = pw @ gcW
__device__ float d_x1[Bv * Sv * H2];            // gcn output (layer1 then layer2)
__device__ float d_V[NRELv * G4];               // bil_W @ rel_embed^T
__device__ float d_score[Bv * Rv];
__device__ float d_pwv[Bv * Sv];
__device__ float d_xsum[Bv * H2];
__device__ float d_attsc[Bv * Sv];
__device__ float d_alpha[Bv * Sv];
__device__ float d_ov[Bv * H2];
__device__ int d_tlen[Bv], d_alen[Bv], d_llen[Bv];
__device__ unsigned d_barr[2 * Sv];             // per-step per-dir arrival counters

// ---------------- barrier reset (run before persistent LSTM each call) ----------------
__global__ void barr_reset() {
    int i = threadIdx.x;
    if (i < 2 * Sv) d_barr[i] = 0u;
}

// ---------------- lengths ----------------
__global__ void len_kernel(const int* __restrict__ ti, const int* __restrict__ ai,
                           const int* __restrict__ li) {
    int b = threadIdx.x;
    if (b >= Bv) return;
    int t = 0;
    for (int s = 0; s < Sv; s++) t += (ti[b * Sv + s] != 0);
    int a = 0;
    for (int s = 0; s < 4; s++) a += (ai[b * 4 + s] != 0);
    int l = 0;
    for (int s = 0; s < 64; s++) l += (li[b * 64 + s] != 0);
    d_tlen[b] = t;
    d_alen[b] = a;
    d_llen[b] = l;
}

// ---------------- embedding gather ----------------
__global__ void embed_kernel(const int* __restrict__ idx, const float* __restrict__ emb) {
    int i = blockIdx.x * 256 + threadIdx.x;
    if (i >= Bv * Sv * Ev) return;
    int e = i % Ev;
    int m = i / Ev;
    d_text[i] = emb[idx[m] * Ev + e];
}

// ---------------- SGEMM: C[M,N] = A[M,K] * B (+bias) ----------------
// BT=true : B is [N,K] row-major (multiply by B^T)
// BT=false: B is [K,N] row-major
// EPI 0: C[m*N+n] = acc (+bias if non-null)
// EPI 1: (Xall) row m = b*Sv + s -> C[(s*Bv+b)*G4 + n] = acc + bias[n]
template <int EPI, bool BT>
__global__ void sgemm_kernel(const float* __restrict__ A, const float* __restrict__ Bm,
                             const float* __restrict__ bias, float* __restrict__ C,
                             int M, int N, int K) {
    __shared__ float As[8 * 128];
    __shared__ float Bs[8 * 64];
    const int m0 = blockIdx.y * 128;
    const int n0 = blockIdx.x * 64;
    const int tid = threadIdx.x;
    const int ty = tid >> 4;   // 0..15 -> m
    const int tx = tid & 15;   // 0..15 -> n

    float acc[8][4];
#pragma unroll
    for (int r = 0; r < 8; r++)
#pragma unroll
        for (int c = 0; c < 4; c++) acc[r][c] = 0.f;

    const int a_m = tid >> 1;          // 0..127
    const int a_k = (tid & 1) * 4;     // 0 or 4

    for (int k0 = 0; k0 < K; k0 += 8) {
        float4 av = make_float4(0.f, 0.f, 0.f, 0.f);
        if (k0 + a_k < K)
            av = *(const float4*)&A[(m0 + a_m) * K + k0 + a_k];
        As[(a_k + 0) * 128 + a_m] = av.x;
        As[(a_k + 1) * 128 + a_m] = av.y;
        As[(a_k + 2) * 128 + a_m] = av.z;
        As[(a_k + 3) * 128 + a_m] = av.w;

        if (BT) {
            int n_l = tid >> 2;
            int kk = (tid & 3) * 2;
            int row = n0 + n_l;
#pragma unroll
            for (int d2 = 0; d2 < 2; d2++) {
                int k = k0 + kk + d2;
                Bs[(kk + d2) * 64 + n_l] = (row < N && k < K) ? Bm[row * K + k] : 0.f;
            }
        } else {
            int kk = tid >> 5;
            int n_l = (tid & 31) * 2;
#pragma unroll
            for (int d2 = 0; d2 < 2; d2++) {
                int n = n_l + d2;
                Bs[kk * 64 + n] = (k0 + kk < K && n0 + n < N) ? Bm[(k0 + kk) * N + n0 + n] : 0.f;
            }
        }
        __syncthreads();

#pragma unroll
        for (int kk = 0; kk < 8; kk++) {
            float4 a0 = *(float4*)&As[kk * 128 + ty * 8];
            float4 a1 = *(float4*)&As[kk * 128 + ty * 8 + 4];
            float4 bv = *(float4*)&Bs[kk * 64 + tx * 4];
            float ar[8] = {a0.x, a0.y, a0.z, a0.w, a1.x, a1.y, a1.z, a1.w};
            float bc[4] = {bv.x, bv.y, bv.z, bv.w};
#pragma unroll
            for (int r = 0; r < 8; r++)
#pragma unroll
                for (int c = 0; c < 4; c++) acc[r][c] += ar[r] * bc[c];
        }
        __syncthreads();
    }

#pragma unroll
    for (int r = 0; r < 8; r++) {
        int row = m0 + ty * 8 + r;
#pragma unroll
        for (int c = 0; c < 4; c++) {
            int col = n0 + tx * 4 + c;
            if (col < N) {
                float v = acc[r][c];
                if (EPI == 0) {
                    if (bias) v += bias[col];
                    C[row * N + col] = v;
                } else {
                    int bb = row >> 8;
                    int ss = row & 255;
                    C[(ss * Bv + bb) * G4 + col] = v + bias[col];
                }
            }
        }
    }
}

// ---------------- persistent BiLSTM: one kernel, software grid barrier per step ------
// grid: 120 blocks (60 per dir), 320 threads. Block owns 5 hidden units (20 W rows).
// All blocks co-resident (120 <= 148 SMs), so spin barrier cannot deadlock.
__global__ void __launch_bounds__(LSTM_THREADS, 1)
lstm_persist(const float* __restrict__ Wfh, const float* __restrict__ Wbh) {
    __shared__ float sW[300 * 20];   // k-major: sW[k*20 + jl]
    __shared__ float sG[20 * 64];    // gate preacts, row-major by jl
    __shared__ float sC[5 * 64];     // cell state

    const int d = blockIdx.x / LSTM_BLOCKS_PER_DIR;
    const int ub5 = (blockIdx.x % LSTM_BLOCKS_PER_DIR) * 5;
    const float* __restrict__ W = (d == 0) ? Wfh : Wbh;
    const int tid = threadIdx.x;

    // stage the 20 rows of W_hh once
    for (int idx = tid; idx < 20 * 300; idx += LSTM_THREADS) {
        int jl = idx / 300, k = idx % 300;
        int j = (jl / 5) * 300 + ub5 + (jl % 5);  // gate*300 + unit
        sW[k * 20 + jl] = W[j * 300 + k];
    }
    if (tid < 5 * 64) sC[tid] = 0.f;
    __syncthreads();

    const int jl = tid % 20;
    const int bq = tid / 20;        // 0..15 (4 batches each)
    const int b0 = bq * 4;
    const int j = (jl / 5) * 300 + ub5 + (jl % 5);
    const int u_l = tid >> 6;       // 0..4 (finalize mapping)
    const int b_f = tid & 63;

    for (int step = 0; step < Sv; step++) {
        const int t_x = (d == 0) ? step : (Sv - 1 - step);
        const float* __restrict__ Xb = d_Xg + (size_t)(d * Sv + t_x) * Bv * G4;

        float acc0 = Xb[(b0 + 0) * G4 + j];
        float acc1 = Xb[(b0 + 1) * G4 + j];
        float acc2 = Xb[(b0 + 2) * G4 + j];
        float acc3 = Xb[(b0 + 3) * G4 + j];

        if (step > 0) {
            const int t_hp = (d == 0) ? (step - 1) : (Sv - step);
            const float4* __restrict__ Hp =
                (const float4*)(d_hseq + (size_t)(d * Sv + t_hp) * Hv * Bv);
#pragma unroll 4
            for (int k = 0; k < 300; k++) {
                float w = sW[k * 20 + jl];
                float4 h4 = __ldg(&Hp[k * 16 + bq]);
                acc0 += w * h4.x;
                acc1 += w * h4.y;
                acc2 += w * h4.z;
                acc3 += w * h4.w;
            }
        }
        sG[jl * 64 + b0 + 0] = acc0;
        sG[jl * 64 + b0 + 1] = acc1;
        sG[jl * 64 + b0 + 2] = acc2;
        sG[jl * 64 + b0 + 3] = acc3;
        __syncthreads();

        // finalize: 5 units x 64 batches (tid < 320 covers all)
        {
            float gi = sG[(0 * 5 + u_l) * 64 + b_f];
            float gf = sG[(1 * 5 + u_l) * 64 + b_f];
            float gg = sG[(2 * 5 + u_l) * 64 + b_f];
            float go = sG[(3 * 5 + u_l) * 64 + b_f];
            float cp = sC[u_l * 64 + b_f];
            float si = 1.f / (1.f + expf(-gi));
            float sf = 1.f / (1.f + expf(-gf));
            float so = 1.f / (1.f + expf(-go));
            float c = sf * cp + si * tanhf(gg);
            sC[u_l * 64 + b_f] = c;
            float h = so * tanhf(c);
            d_hseq[((size_t)(d * Sv + t_x) * Hv + ub5 + u_l) * 64 + b_f] = h;
        }

        // grid barrier over this direction's 60 blocks (step-indexed counter)
        __syncthreads();
        if (tid == 0) {
            __threadfence();
            unsigned* ctr = &d_barr[d * Sv + step];
            atomicAdd(ctr, 1u);
            while (*(volatile unsigned*)ctr < (unsigned)LSTM_BLOCKS_PER_DIR) {}
            __threadfence();
        }
        __syncthreads();
    }
}

// ---------------- assemble text_out [b][s][600] ----------------
__global__ void assemble_to() {
    int i = blockIdx.x * 256 + threadIdx.x;
    if (i >= Bv * Sv * H2) return;
    int h = i % H2;
    int bs = i / H2;
    int s = bs % Sv;
    int b = bs / Sv;
    int dsel = (h >= Hv) ? 1 : 0;
    int u = h - dsel * Hv;
    d_to[i] = d_hseq[((size_t)(dsel * Sv + s) * Hv + u) * 64 + b];
}

// ---------------- V = bil_W @ rel_embed^T ----------------
__global__ void vprep(const float* __restrict__ bw, const float* __restrict__ re) {
    int r = blockIdx.x;
    for (int i = threadIdx.x; i < G4; i += 256) {
        float a = 0.f;
#pragma unroll
        for (int jj = 0; jj < RELDv; jj++) a += bw[i * RELDv + jj] * re[r * RELDv + jj];
        d_V[r * G4 + i] = a;
    }
}

// ---------------- relation scores (warp per (b,r)) ----------------
__global__ void relscore(const int* __restrict__ head, const int* __restrict__ behead,
                         const int* __restrict__ rel, const float* __restrict__ bilb) {
    int g = blockIdx.x * 8 + (threadIdx.x >> 5);
    int lane = threadIdx.x & 31;
    if (g >= Bv * Rv) return;
    int b = g / Rv;
    int rr = rel[g];
    float dotv = 0.f;
    if (rr != 0) {
        int h1 = head[g], h2 = behead[g];
        const float* __restrict__ n1 = d_to + (size_t)(b * Sv + h1) * H2;
        const float* __restrict__ n2 = d_to + (size_t)(b * Sv + h2) * H2;
        const float* __restrict__ V = d_V + rr * G4;
        for (int i = lane; i < H2; i += 32) dotv += n1[i] * V[i] + n2[i] * V[H2 + i];
    }
#pragma unroll
    for (int o = 16; o; o >>= 1) dotv += __shfl_down_sync(0xffffffffu, dotv, o);
    if (lane == 0) d_score[g] = 1.f / (1.f + expf(-(dotv + bilb[0])));
}

// ---------------- position weights ----------------
__global__ void pwv_kernel() {
    int b = blockIdx.x;
    int s = threadIdx.x;
    float tl = (float)d_tlen[b];
    float al = (float)d_alen[b];
    float l0 = (float)d_llen[b];
    float l1 = l0 + al - 1.f;
    float ctx = tl - al;
    float jf = (float)s;
    float w;
    if (jf < l0) w = 1.f - (l0 - jf) / ctx;
    else if (jf <= l1) w = 0.f;
    else if (jf < tl) w = 1.f - (jf - l1) / ctx;
    else w = 0.f;
    d_pwv[b * Sv + s] = w;
}

__global__ void pw_apply(const float* __restrict__ src) {
    int i = blockIdx.x * 256 + threadIdx.x;
    if (i >= Bv * Sv * H2) return;
    d_pw[i] = src[i] * d_pwv[i / H2];
}

// ---------------- sparse GCN apply: out = relu(adj@hidden/den + bias) ----------------
__global__ void gcn_apply(const int* __restrict__ head, const int* __restrict__ behead,
                          const float* __restrict__ bias, float* __restrict__ out) {
    int bs = blockIdx.x;
    int b = bs >> 8;
    int s1 = bs & 255;
    const int* hd = head + b * Rv;
    int L = 0, Rr = Rv;
    while (L < Rr) { int m = (L + Rr) >> 1; if (hd[m] < s1) L = m + 1; else Rr = m; }
    int lo = L;
    Rr = Rv;
    while (L < Rr) { int m = (L + Rr) >> 1; if (hd[m] <= s1) L = m + 1; else Rr = m; }
    int hi = L;
    float den = 1.f;
    for (int r = lo; r < hi; r++) den += d_score[b * Rv + r];
    float inv = 1.f / den;
    for (int h = threadIdx.x; h < H2; h += 128) {
        float a = 0.f;
        for (int r = lo; r < hi; r++)
            a += d_score[b * Rv + r] * d_hid[(size_t)(b * Sv + behead[b * Rv + r]) * H2 + h];
        float v = a * inv + bias[h];
        out[(size_t)(b * Sv + s1) * H2 + h] = fmaxf(v, 0.f);
    }
}

// ---------------- attention ----------------
__global__ void xsum_kernel(const float* __restrict__ x) {
    int b = blockIdx.x;
    int h = threadIdx.x;
    if (h >= H2) return;
    int l0 = d_llen[b];
    int l1 = l0 + d_alen[b] - 1;
    if (l1 > Sv - 1) l1 = Sv - 1;
    float a = 0.f;
    for (int s = l0; s <= l1; s++) a += x[(size_t)(b * Sv + s) * H2 + h];
    d_xsum[b * H2 + h] = a;
}

__global__ void attscore() {
    int g = blockIdx.x * 8 + (threadIdx.x >> 5);
    int lane = threadIdx.x & 31;
    if (g >= Bv * Sv) return;
    int b = g >> 8;
    float a = 0.f;
    for (int i = lane; i < H2; i += 32) a += d_xsum[b * H2 + i] * d_to[(size_t)g * H2 + i];
#pragma unroll
    for (int o = 16; o; o >>= 1) a += __shfl_down_sync(0xffffffffu, a, o);
    if (lane == 0) d_attsc[g] = a;
}

__global__ void softmax_kernel() {
    __shared__ float red[256];
    int b = blockIdx.x;
    int tid = threadIdx.x;
    float v = d_attsc[b * Sv + tid];
    red[tid] = v;
    __syncthreads();
    for (int o = 128; o; o >>= 1) {
        if (tid < o) red[tid] = fmaxf(red[tid], red[tid + o]);
        __syncthreads();
    }
    float smax = red[0];
    __syncthreads();
    float e = expf(v - smax);
    red[tid] = e;
    __syncthreads();
    for (int o = 128; o; o >>= 1) {
        if (tid < o) red[tid] += red[tid + o];
        __syncthreads();
    }
    d_alpha[b * Sv + tid] = e / red[0];
}

__global__ void outvec_kernel() {
    int b = blockIdx.x;
    int h = threadIdx.x;
    if (h >= H2) return;
    float a = 0.f;
    for (int s = 0; s < Sv; s++) a += d_alpha[b * Sv + s] * d_to[(size_t)(b * Sv + s) * H2 + h];
    d_ov[b * H2 + h] = a;
}

__global__ void final_fc(const float* __restrict__ fcW, const float* __restrict__ fcb,
                         float* __restrict__ out) {
    int b = blockIdx.x;
    int p = threadIdx.x >> 5;
    int lane = threadIdx.x & 31;
    if (p >= 3) return;
    float a = 0.f;
    for (int h = lane; h < H2; h += 32) a += d_ov[b * H2 + h] * fcW[h * 3 + p];
#pragma unroll
    for (int o = 16; o; o >>= 1) a += __shfl_down_sync(0xffffffffu, a, o);
    if (lane == 0) out[b * 3 + p] = a + fcb[p];
}

// ---------------- launch ----------------
extern "C" void kernel_launch(void* const* d_in, const int* in_sizes, int n_in,
                              void* d_out, int out_size) {
    const int* text_indices = (const int*)d_in[0];
    const int* aspect_indices = (const int*)d_in[1];
    const int* left_indices = (const int*)d_in[2];
    // d_in[3] = adj (dense) — unused: its nonzeros are exactly (head, behead)
    const int* head_vector = (const int*)d_in[4];
    const int* behead_vector = (const int*)d_in[5];
    const int* relation_vector = (const int*)d_in[6];
    const float* embed_table = (const float*)d_in[7];
    const float* rel_embed = (const float*)d_in[8];
    const float* Wf_ih = (const float*)d_in[9];
    const float* Wf_hh = (const float*)d_in[10];
    const float* bf = (const float*)d_in[11];
    const float* Wb_ih = (const float*)d_in[12];
    const float* Wb_hh = (const float*)d_in[13];
    const float* bb = (const float*)d_in[14];
    const float* bil_W = (const float*)d_in[15];
    const float* bil_b = (const float*)d_in[16];
    const float* gc1_W = (const float*)d_in[17];
    const float* gc1_b = (const float*)d_in[18];
    const float* gc2_W = (const float*)d_in[19];
    const float* gc2_b = (const float*)d_in[20];
    const float* fc_W = (const float*)d_in[21];
    const float* fc_b = (const float*)d_in[22];
    float* out = (float*)d_out;

    float* p_text;  cudaGetSymbolAddress((void**)&p_text, d_text);
    float* p_Xg;    cudaGetSymbolAddress((void**)&p_Xg, d_Xg);
    float* p_to;    cudaGetSymbolAddress((void**)&p_to, d_to);
    float* p_pw;    cudaGetSymbolAddress((void**)&p_pw, d_pw);
    float* p_hid;   cudaGetSymbolAddress((void**)&p_hid, d_hid);
    float* p_x1;    cudaGetSymbolAddress((void**)&p_x1, d_x1);

    barr_reset<<<1, 512>>>();
    len_kernel<<<1, 64>>>(text_indices, aspect_indices, left_indices);
    embed_kernel<<<(Bv * Sv * Ev + 255) / 256, 256>>>(text_indices, embed_table);

    // input-side gate GEMMs: [16384,300] x [300,1200]^T (+bias), scattered to [s][b][j]
    {
        dim3 g((G4 + 63) / 64, (Bv * Sv) / 128);
        sgemm_kernel<1, true><<<g, 256>>>(p_text, Wf_ih, bf, p_Xg, Bv * Sv, G4, Ev);
        sgemm_kernel<1, true><<<g, 256>>>(p_text, Wb_ih, bb, p_Xg + (size_t)Sv * Bv * G4,
                                          Bv * Sv, G4, Ev);
    }

    // persistent recurrence: single kernel, 256 internal steps
    lstm_persist<<<2 * LSTM_BLOCKS_PER_DIR, LSTM_THREADS>>>(Wf_hh, Wb_hh);

    assemble_to<<<(Bv * Sv * H2 + 255) / 256, 256>>>();

    // relation scoring
    vprep<<<NRELv, 256>>>(bil_W, rel_embed);
    relscore<<<(Bv * Rv) / 8, 256>>>(head_vector, behead_vector, relation_vector, bil_b);

    pwv_kernel<<<Bv, Sv>>>();

    // GCN layer 1
    pw_apply<<<(Bv * Sv * H2 + 255) / 256, 256>>>(p_to);
    {
        dim3 g((H2 + 63) / 64, (Bv * Sv) / 128);
        sgemm_kernel<0, false><<<g, 256>>>(p_pw, gc1_W, nullptr, p_hid, Bv * Sv, H2, H2);
    }
    gcn_apply<<<Bv * Sv, 128>>>(head_vector, behead_vector, gc1_b, p_x1);

    // GCN layer 2
    pw_apply<<<(Bv * Sv * H2 + 255) / 256, 256>>>(p_x1);
    {
        dim3 g((H2 + 63) / 64, (Bv * Sv) / 128);
        sgemm_kernel<0, false><<<g, 256>>>(p_pw, gc2_W, nullptr, p_hid, Bv * Sv, H2, H2);
    }
    gcn_apply<<<Bv * Sv, 128>>>(head_vector, behead_vector, gc2_b, p_x1);

    // attention (alpha_mat collapses: sum over axis 1 first)
    xsum_kernel<<<Bv, 640>>>(p_x1);
    attscore<<<(Bv * Sv) / 8, 256>>>();
    softmax_kernel<<<Bv, 256>>>();
    outvec_kernel<<<Bv, 640>>>();
    final_fc<<<Bv, 96>>>(fc_W, fc_b, out);

    (void)in_sizes; (void)n_in; (void)out_size;
}

// round 3
// speedup vs baseline: 1.8323x; 1.6056x over previous
#include <cuda_runtime.h>
#include <math.h>

#define Bv 64
#define Sv 256
#define Ev 300
#define Hv 300
#define H2 600
#define G4 1200
#define Rv 512
#define NRELv 46
#define RELDv 50

#define LSTM_BLOCKS_PER_DIR 60   // 5 units per block
#define LSTM_THREADS 320         // 20 rows x 16 batch-quads
#define KPAD 304                 // k padded to multiple of 16

// ---------------- device scratch (no allocations allowed) ----------------
__device__ float d_text[Bv * Sv * Ev];              // [b][s][e]
__device__ float d_Xg[2 * Sv * Bv * G4];            // [dir][s][b][1200]
__device__ float d_hseq[2 * Sv * Hv * Bv + 256];    // [dir][t][u][b] (+pad for k-overread)
__device__ float d_to[Bv * Sv * H2];                // text_out [b][s][600]
__device__ float d_pw[Bv * Sv * H2];
__device__ float d_hid[Bv * Sv * H2];
__device__ float d_x1[Bv * Sv * H2];
__device__ float d_V[NRELv * G4];
__device__ float d_score[Bv * Rv];
__device__ float d_pwv[Bv * Sv];
__device__ float d_xsum[Bv * H2];
__device__ float d_attsc[Bv * Sv];
__device__ float d_alpha[Bv * Sv];
__device__ float d_ov[Bv * H2];
__device__ int d_tlen[Bv], d_alen[Bv], d_llen[Bv];
__device__ unsigned d_barr[2 * Sv];

__device__ __forceinline__ unsigned ld_acquire(const unsigned* p) {
    unsigned v;
    asm volatile("ld.acquire.gpu.global.u32 %0, [%1];" : "=r"(v) : "l"(p) : "memory");
    return v;
}

// ---------------- barrier reset ----------------
__global__ void barr_reset() {
    int i = threadIdx.x;
    if (i < 2 * Sv) d_barr[i] = 0u;
}

// ---------------- lengths ----------------
__global__ void len_kernel(const int* __restrict__ ti, const int* __restrict__ ai,
                           const int* __restrict__ li) {
    int b = threadIdx.x;
    if (b >= Bv) return;
    int t = 0;
    for (int s = 0; s < Sv; s++) t += (ti[b * Sv + s] != 0);
    int a = 0;
    for (int s = 0; s < 4; s++) a += (ai[b * 4 + s] != 0);
    int l = 0;
    for (int s = 0; s < 64; s++) l += (li[b * 64 + s] != 0);
    d_tlen[b] = t;
    d_alen[b] = a;
    d_llen[b] = l;
}

// ---------------- embedding gather ----------------
__global__ void embed_kernel(const int* __restrict__ idx, const float* __restrict__ emb) {
    int i = blockIdx.x * 256 + threadIdx.x;
    if (i >= Bv * Sv * Ev) return;
    int e = i % Ev;
    int m = i / Ev;
    d_text[i] = emb[idx[m] * Ev + e];
}

// ---------------- SGEMM ----------------
template <int EPI, bool BT>
__global__ void sgemm_kernel(const float* __restrict__ A, const float* __restrict__ Bm,
                             const float* __restrict__ bias, float* __restrict__ C,
                             int M, int N, int K) {
    __shared__ float As[8 * 128];
    __shared__ float Bs[8 * 64];
    const int m0 = blockIdx.y * 128;
    const int n0 = blockIdx.x * 64;
    const int tid = threadIdx.x;
    const int ty = tid >> 4;
    const int tx = tid & 15;

    float acc[8][4];
#pragma unroll
    for (int r = 0; r < 8; r++)
#pragma unroll
        for (int c = 0; c < 4; c++) acc[r][c] = 0.f;

    const int a_m = tid >> 1;
    const int a_k = (tid & 1) * 4;

    for (int k0 = 0; k0 < K; k0 += 8) {
        float4 av = make_float4(0.f, 0.f, 0.f, 0.f);
        if (k0 + a_k < K)
            av = *(const float4*)&A[(m0 + a_m) * K + k0 + a_k];
        As[(a_k + 0) * 128 + a_m] = av.x;
        As[(a_k + 1) * 128 + a_m] = av.y;
        As[(a_k + 2) * 128 + a_m] = av.z;
        As[(a_k + 3) * 128 + a_m] = av.w;

        if (BT) {
            int n_l = tid >> 2;
            int kk = (tid & 3) * 2;
            int row = n0 + n_l;
#pragma unroll
            for (int d2 = 0; d2 < 2; d2++) {
                int k = k0 + kk + d2;
                Bs[(kk + d2) * 64 + n_l] = (row < N && k < K) ? Bm[row * K + k] : 0.f;
            }
        } else {
            int kk = tid >> 5;
            int n_l = (tid & 31) * 2;
#pragma unroll
            for (int d2 = 0; d2 < 2; d2++) {
                int n = n_l + d2;
                Bs[kk * 64 + n] = (k0 + kk < K && n0 + n < N) ? Bm[(k0 + kk) * N + n0 + n] : 0.f;
            }
        }
        __syncthreads();

#pragma unroll
        for (int kk = 0; kk < 8; kk++) {
            float4 a0 = *(float4*)&As[kk * 128 + ty * 8];
            float4 a1 = *(float4*)&As[kk * 128 + ty * 8 + 4];
            float4 bv = *(float4*)&Bs[kk * 64 + tx * 4];
            float ar[8] = {a0.x, a0.y, a0.z, a0.w, a1.x, a1.y, a1.z, a1.w};
            float bc[4] = {bv.x, bv.y, bv.z, bv.w};
#pragma unroll
            for (int r = 0; r < 8; r++)
#pragma unroll
                for (int c = 0; c < 4; c++) acc[r][c] += ar[r] * bc[c];
        }
        __syncthreads();
    }

#pragma unroll
    for (int r = 0; r < 8; r++) {
        int row = m0 + ty * 8 + r;
#pragma unroll
        for (int c = 0; c < 4; c++) {
            int col = n0 + tx * 4 + c;
            if (col < N) {
                float v = acc[r][c];
                if (EPI == 0) {
                    if (bias) v += bias[col];
                    C[row * N + col] = v;
                } else {
                    int bb = row >> 8;
                    int ss = row & 255;
                    C[(size_t)(ss * Bv + bb) * G4 + col] = v + bias[col];
                }
            }
        }
    }
}

// ---------------- persistent BiLSTM with double-buffered k-loop ----------------
__global__ void __launch_bounds__(LSTM_THREADS, 1)
lstm_persist(const float* __restrict__ Wfh, const float* __restrict__ Wbh) {
    __shared__ float sW[KPAD * 20];   // k-major: sW[k*20 + jl], zero-padded k>=300
    __shared__ float sG[20 * 64];
    __shared__ float sC[5 * 64];

    const int d = blockIdx.x / LSTM_BLOCKS_PER_DIR;
    const int ub5 = (blockIdx.x % LSTM_BLOCKS_PER_DIR) * 5;
    const float* __restrict__ W = (d == 0) ? Wfh : Wbh;
    const int tid = threadIdx.x;

    for (int idx = tid; idx < 20 * KPAD; idx += LSTM_THREADS) {
        int jl = idx / KPAD, k = idx % KPAD;
        int j = (jl / 5) * 300 + ub5 + (jl % 5);
        sW[k * 20 + jl] = (k < 300) ? W[j * 300 + k] : 0.f;
    }
    if (tid < 5 * 64) sC[tid] = 0.f;
    __syncthreads();

    const int jl = tid % 20;
    const int bq = tid / 20;        // 0..15
    const int b0 = bq * 4;
    const int j = (jl / 5) * 300 + ub5 + (jl % 5);
    const int u_l = tid >> 6;       // 0..4
    const int b_f = tid & 63;
    const unsigned nblk = (unsigned)LSTM_BLOCKS_PER_DIR;

    // prefetch X for step 0
    float px0, px1, px2, px3;
    {
        const int t0 = (d == 0) ? 0 : (Sv - 1);
        const float* __restrict__ Xb = d_Xg + (size_t)(d * Sv + t0) * Bv * G4;
        px0 = Xb[(b0 + 0) * G4 + j];
        px1 = Xb[(b0 + 1) * G4 + j];
        px2 = Xb[(b0 + 2) * G4 + j];
        px3 = Xb[(b0 + 3) * G4 + j];
    }

    for (int step = 0; step < Sv; step++) {
        const int t_x = (d == 0) ? step : (Sv - 1 - step);

        float acc0 = px0, acc1 = px1, acc2 = px2, acc3 = px3;

        if (step > 0) {
            const int t_hp = (d == 0) ? (step - 1) : (Sv - step);
            const float4* __restrict__ Hp =
                (const float4*)(d_hseq + (size_t)(d * Sv + t_hp) * Hv * Bv);

            float4 Ar[8], Br[8];
#pragma unroll
            for (int t = 0; t < 8; t++) Ar[t] = __ldg(&Hp[t * 16 + bq]);

#pragma unroll 1
            for (int kb = 0; kb < KPAD; kb += 16) {
#pragma unroll
                for (int t = 0; t < 8; t++) Br[t] = __ldg(&Hp[(kb + 8 + t) * 16 + bq]);
#pragma unroll
                for (int t = 0; t < 8; t++) {
                    float w = sW[(kb + t) * 20 + jl];
                    acc0 += w * Ar[t].x;
                    acc1 += w * Ar[t].y;
                    acc2 += w * Ar[t].z;
                    acc3 += w * Ar[t].w;
                }
                if (kb + 16 < KPAD) {
#pragma unroll
                    for (int t = 0; t < 8; t++) Ar[t] = __ldg(&Hp[(kb + 16 + t) * 16 + bq]);
                }
#pragma unroll
                for (int t = 0; t < 8; t++) {
                    float w = sW[(kb + 8 + t) * 20 + jl];
                    acc0 += w * Br[t].x;
                    acc1 += w * Br[t].y;
                    acc2 += w * Br[t].z;
                    acc3 += w * Br[t].w;
                }
            }
        }
        sG[jl * 64 + b0 + 0] = acc0;
        sG[jl * 64 + b0 + 1] = acc1;
        sG[jl * 64 + b0 + 2] = acc2;
        sG[jl * 64 + b0 + 3] = acc3;
        __syncthreads();

        // finalize: 5 units x 64 batches
        {
            float gi = sG[(0 * 5 + u_l) * 64 + b_f];
            float gf = sG[(1 * 5 + u_l) * 64 + b_f];
            float gg = sG[(2 * 5 + u_l) * 64 + b_f];
            float go = sG[(3 * 5 + u_l) * 64 + b_f];
            float cp = sC[u_l * 64 + b_f];
            float si = 1.f / (1.f + expf(-gi));
            float sf = 1.f / (1.f + expf(-gf));
            float so = 1.f / (1.f + expf(-go));
            float c = sf * cp + si * tanhf(gg);
            sC[u_l * 64 + b_f] = c;
            float h = so * tanhf(c);
            d_hseq[((size_t)(d * Sv + t_x) * Hv + ub5 + u_l) * 64 + b_f] = h;
        }

        // prefetch X for step+1 (independent of h) — hides DRAM latency under barrier
        if (step + 1 < Sv) {
            const int tn = (d == 0) ? (step + 1) : (Sv - 2 - step);
            const float* __restrict__ Xn = d_Xg + (size_t)(d * Sv + tn) * Bv * G4;
            px0 = Xn[(b0 + 0) * G4 + j];
            px1 = Xn[(b0 + 1) * G4 + j];
            px2 = Xn[(b0 + 2) * G4 + j];
            px3 = Xn[(b0 + 3) * G4 + j];
        }

        // grid barrier over this direction's blocks
        __syncthreads();
        if (tid == 0) {
            __threadfence();
            atomicAdd(&d_barr[d * Sv + step], 1u);
        }
        const unsigned* ctr = &d_barr[d * Sv + step];
        while (ld_acquire(ctr) < nblk) {}
    }
}

// ---------------- assemble text_out [b][s][600] ----------------
__global__ void assemble_to() {
    int i = blockIdx.x * 256 + threadIdx.x;
    if (i >= Bv * Sv * H2) return;
    int h = i % H2;
    int bs = i / H2;
    int s = bs % Sv;
    int b = bs / Sv;
    int dsel = (h >= Hv) ? 1 : 0;
    int u = h - dsel * Hv;
    d_to[i] = d_hseq[((size_t)(dsel * Sv + s) * Hv + u) * 64 + b];
}

// ---------------- V = bil_W @ rel_embed^T ----------------
__global__ void vprep(const float* __restrict__ bw, const float* __restrict__ re) {
    int r = blockIdx.x;
    for (int i = threadIdx.x; i < G4; i += 256) {
        float a = 0.f;
#pragma unroll
        for (int jj = 0; jj < RELDv; jj++) a += bw[i * RELDv + jj] * re[r * RELDv + jj];
        d_V[r * G4 + i] = a;
    }
}

// ---------------- relation scores ----------------
__global__ void relscore(const int* __restrict__ head, const int* __restrict__ behead,
                         const int* __restrict__ rel, const float* __restrict__ bilb) {
    int g = blockIdx.x * 8 + (threadIdx.x >> 5);
    int lane = threadIdx.x & 31;
    if (g >= Bv * Rv) return;
    int b = g / Rv;
    int rr = rel[g];
    float dotv = 0.f;
    if (rr != 0) {
        int h1 = head[g], h2 = behead[g];
        const float* __restrict__ n1 = d_to + (size_t)(b * Sv + h1) * H2;
        const float* __restrict__ n2 = d_to + (size_t)(b * Sv + h2) * H2;
        const float* __restrict__ V = d_V + rr * G4;
        for (int i = lane; i < H2; i += 32) dotv += n1[i] * V[i] + n2[i] * V[H2 + i];
    }
#pragma unroll
    for (int o = 16; o; o >>= 1) dotv += __shfl_down_sync(0xffffffffu, dotv, o);
    if (lane == 0) d_score[g] = 1.f / (1.f + expf(-(dotv + bilb[0])));
}

// ---------------- position weights ----------------
__global__ void pwv_kernel() {
    int b = blockIdx.x;
    int s = threadIdx.x;
    float tl = (float)d_tlen[b];
    float al = (float)d_alen[b];
    float l0 = (float)d_llen[b];
    float l1 = l0 + al - 1.f;
    float ctx = tl - al;
    float jf = (float)s;
    float w;
    if (jf < l0) w = 1.f - (l0 - jf) / ctx;
    else if (jf <= l1) w = 0.f;
    else if (jf < tl) w = 1.f - (jf - l1) / ctx;
    else w = 0.f;
    d_pwv[b * Sv + s] = w;
}

__global__ void pw_apply(const float* __restrict__ src) {
    int i = blockIdx.x * 256 + threadIdx.x;
    if (i >= Bv * Sv * H2) return;
    d_pw[i] = src[i] * d_pwv[i / H2];
}

// ---------------- sparse GCN apply ----------------
__global__ void gcn_apply(const int* __restrict__ head, const int* __restrict__ behead,
                          const float* __restrict__ bias, float* __restrict__ out) {
    int bs = blockIdx.x;
    int b = bs >> 8;
    int s1 = bs & 255;
    const int* hd = head + b * Rv;
    int L = 0, Rr = Rv;
    while (L < Rr) { int m = (L + Rr) >> 1; if (hd[m] < s1) L = m + 1; else Rr = m; }
    int lo = L;
    Rr = Rv;
    while (L < Rr) { int m = (L + Rr) >> 1; if (hd[m] <= s1) L = m + 1; else Rr = m; }
    int hi = L;
    float den = 1.f;
    for (int r = lo; r < hi; r++) den += d_score[b * Rv + r];
    float inv = 1.f / den;
    for (int h = threadIdx.x; h < H2; h += 128) {
        float a = 0.f;
        for (int r = lo; r < hi; r++)
            a += d_score[b * Rv + r] * d_hid[(size_t)(b * Sv + behead[b * Rv + r]) * H2 + h];
        float v = a * inv + bias[h];
        out[(size_t)(b * Sv + s1) * H2 + h] = fmaxf(v, 0.f);
    }
}

// ---------------- attention ----------------
__global__ void xsum_kernel(const float* __restrict__ x) {
    int b = blockIdx.x;
    int h = threadIdx.x;
    if (h >= H2) return;
    int l0 = d_llen[b];
    int l1 = l0 + d_alen[b] - 1;
    if (l1 > Sv - 1) l1 = Sv - 1;
    float a = 0.f;
    for (int s = l0; s <= l1; s++) a += x[(size_t)(b * Sv + s) * H2 + h];
    d_xsum[b * H2 + h] = a;
}

__global__ void attscore() {
    int g = blockIdx.x * 8 + (threadIdx.x >> 5);
    int lane = threadIdx.x & 31;
    if (g >= Bv * Sv) return;
    int b = g >> 8;
    float a = 0.f;
    for (int i = lane; i < H2; i += 32) a += d_xsum[b * H2 + i] * d_to[(size_t)g * H2 + i];
#pragma unroll
    for (int o = 16; o; o >>= 1) a += __shfl_down_sync(0xffffffffu, a, o);
    if (lane == 0) d_attsc[g] = a;
}

__global__ void softmax_kernel() {
    __shared__ float red[256];
    int b = blockIdx.x;
    int tid = threadIdx.x;
    float v = d_attsc[b * Sv + tid];
    red[tid] = v;
    __syncthreads();
    for (int o = 128; o; o >>= 1) {
        if (tid < o) red[tid] = fmaxf(red[tid], red[tid + o]);
        __syncthreads();
    }
    float smax = red[0];
    __syncthreads();
    float e = expf(v - smax);
    red[tid] = e;
    __syncthreads();
    for (int o = 128; o; o >>= 1) {
        if (tid < o) red[tid] += red[tid + o];
        __syncthreads();
    }
    d_alpha[b * Sv + tid] = e / red[0];
}

__global__ void outvec_kernel() {
    int b = blockIdx.x;
    int h = threadIdx.x;
    if (h >= H2) return;
    float a = 0.f;
    for (int s = 0; s < Sv; s++) a += d_alpha[b * Sv + s] * d_to[(size_t)(b * Sv + s) * H2 + h];
    d_ov[b * H2 + h] = a;
}

__global__ void final_fc(const float* __restrict__ fcW, const float* __restrict__ fcb,
                         float* __restrict__ out) {
    int b = blockIdx.x;
    int p = threadIdx.x >> 5;
    int lane = threadIdx.x & 31;
    if (p >= 3) return;
    float a = 0.f;
    for (int h = lane; h < H2; h += 32) a += d_ov[b * H2 + h] * fcW[h * 3 + p];
#pragma unroll
    for (int o = 16; o; o >>= 1) a += __shfl_down_sync(0xffffffffu, a, o);
    if (lane == 0) out[b * 3 + p] = a + fcb[p];
}

// ---------------- launch ----------------
extern "C" void kernel_launch(void* const* d_in, const int* in_sizes, int n_in,
                              void* d_out, int out_size) {
    const int* text_indices = (const int*)d_in[0];
    const int* aspect_indices = (const int*)d_in[1];
    const int* left_indices = (const int*)d_in[2];
    // d_in[3] = adj (dense) — unused
    const int* head_vector = (const int*)d_in[4];
    const int* behead_vector = (const int*)d_in[5];
    const int* relation_vector = (const int*)d_in[6];
    const float* embed_table = (const float*)d_in[7];
    const float* rel_embed = (const float*)d_in[8];
    const float* Wf_ih = (const float*)d_in[9];
    const float* Wf_hh = (const float*)d_in[10];
    const float* bf = (const float*)d_in[11];
    const float* Wb_ih = (const float*)d_in[12];
    const float* Wb_hh = (const float*)d_in[13];
    const float* bb = (const float*)d_in[14];
    const float* bil_W = (const float*)d_in[15];
    const float* bil_b = (const float*)d_in[16];
    const float* gc1_W = (const float*)d_in[17];
    const float* gc1_b = (const float*)d_in[18];
    const float* gc2_W = (const float*)d_in[19];
    const float* gc2_b = (const float*)d_in[20];
    const float* fc_W = (const float*)d_in[21];
    const float* fc_b = (const float*)d_in[22];
    float* out = (float*)d_out;

    float* p_text;  cudaGetSymbolAddress((void**)&p_text, d_text);
    float* p_Xg;    cudaGetSymbolAddress((void**)&p_Xg, d_Xg);
    float* p_to;    cudaGetSymbolAddress((void**)&p_to, d_to);
    float* p_pw;    cudaGetSymbolAddress((void**)&p_pw, d_pw);
    float* p_hid;   cudaGetSymbolAddress((void**)&p_hid, d_hid);
    float* p_x1;    cudaGetSymbolAddress((void**)&p_x1, d_x1);

    len_kernel<<<1, 64>>>(text_indices, aspect_indices, left_indices);
    embed_kernel<<<(Bv * Sv * Ev + 255) / 256, 256>>>(text_indices, embed_table);

    {
        dim3 g((G4 + 63) / 64, (Bv * Sv) / 128);
        sgemm_kernel<1, true><<<g, 256>>>(p_text, Wf_ih, bf, p_Xg, Bv * Sv, G4, Ev);
        sgemm_kernel<1, true><<<g, 256>>>(p_text, Wb_ih, bb, p_Xg + (size_t)Sv * Bv * G4,
                                          Bv * Sv, G4, Ev);
    }

    barr_reset<<<1, 512>>>();
    lstm_persist<<<2 * LSTM_BLOCKS_PER_DIR, LSTM_THREADS>>>(Wf_hh, Wb_hh);

    assemble_to<<<(Bv * Sv * H2 + 255) / 256, 256>>>();

    vprep<<<NRELv, 256>>>(bil_W, rel_embed);
    relscore<<<(Bv * Rv) / 8, 256>>>(head_vector, behead_vector, relation_vector, bil_b);

    pwv_kernel<<<Bv, Sv>>>();

    pw_apply<<<(Bv * Sv * H2 + 255) / 256, 256>>>(p_to);
    {
        dim3 g((H2 + 63) / 64, (Bv * Sv) / 128);
        sgemm_kernel<0, false><<<g, 256>>>(p_pw, gc1_W, nullptr, p_hid, Bv * Sv, H2, H2);
    }
    gcn_apply<<<Bv * Sv, 128>>>(head_vector, behead_vector, gc1_b, p_x1);

    pw_apply<<<(Bv * Sv * H2 + 255) / 256, 256>>>(p_x1);
    {
        dim3 g((H2 + 63) / 64, (Bv * Sv) / 128);
        sgemm_kernel<0, false><<<g, 256>>>(p_pw, gc2_W, nullptr, p_hid, Bv * Sv, H2, H2);
    }
    gcn_apply<<<Bv * Sv, 128>>>(head_vector, behead_vector, gc2_b, p_x1);

    xsum_kernel<<<Bv, 640>>>(p_x1);
    attscore<<<(Bv * Sv) / 8, 256>>>();
    softmax_kernel<<<Bv, 256>>>();
    outvec_kernel<<<Bv, 640>>>();
    final_fc<<<Bv, 96>>>(fc_W, fc_b, out);

    (void)in_sizes; (void)n_in; (void)out_size;
}

// round 5
// speedup vs baseline: 2.0132x; 1.0987x over previous
#include <cuda_runtime.h>
#include <math.h>

#define Bv 64
#define Sv 256
#define Ev 300
#define Hv 300
#define H2 600
#define G4 1200
#define Rv 512
#define NRELv 46
#define RELDv 50

#define LSTM_BLOCKS_PER_DIR 60   // 5 units per block
#define LSTM_THREADS 320         // 20 rows x 16 batch-quads

// dynamic smem layout for lstm_persist (floats)
#define SH_OFF 0                 // sH [300][64]
#define SW_OFF 19200             // sW [300][20]
#define SG_OFF (19200 + 6000)    // sG [20][64]
#define SC_OFF (SG_OFF + 1280)   // sC [5][64]
#define LSTM_SMEM_BYTES ((SC_OFF + 320) * 4)

// ---------------- device scratch (no allocations allowed) ----------------
__device__ float d_text[Bv * Sv * Ev];              // [b][s][e]
__device__ float d_Xg[2 * Sv * Bv * G4];            // [dir][s][b][1200]
__device__ float d_hseq[2 * Sv * Hv * Bv];          // [dir][t][u][b]
__device__ float d_to[Bv * Sv * H2];                // text_out [b][s][600]
__device__ float d_hid[Bv * Sv * H2];
__device__ float d_x1[Bv * Sv * H2];
__device__ float d_V[NRELv * G4];
__device__ float d_score[Bv * Rv];
__device__ float d_pwv[Bv * Sv];
__device__ float d_xsum[Bv * H2];
__device__ float d_attsc[Bv * Sv];
__device__ float d_alpha[Bv * Sv];
__device__ float d_ov[Bv * H2];
__device__ int d_tlen[Bv], d_alen[Bv], d_llen[Bv];
__device__ unsigned d_barr[2 * Sv];

__device__ __forceinline__ unsigned ld_acquire(const unsigned* p) {
    unsigned v;
    asm volatile("ld.acquire.gpu.global.u32 %0, [%1];" : "=r"(v) : "l"(p) : "memory");
    return v;
}

// ---------------- barrier reset ----------------
__global__ void barr_reset() {
    int i = threadIdx.x;
    if (i < 2 * Sv) d_barr[i] = 0u;
}

// ---------------- lengths ----------------
__global__ void len_kernel(const int* __restrict__ ti, const int* __restrict__ ai,
                           const int* __restrict__ li) {
    int b = threadIdx.x;
    if (b >= Bv) return;
    int t = 0;
    for (int s = 0; s < Sv; s++) t += (ti[b * Sv + s] != 0);
    int a = 0;
    for (int s = 0; s < 4; s++) a += (ai[b * 4 + s] != 0);
    int l = 0;
    for (int s = 0; s < 64; s++) l += (li[b * 64 + s] != 0);
    d_tlen[b] = t;
    d_alen[b] = a;
    d_llen[b] = l;
}

// ---------------- embedding gather ----------------
__global__ void embed_kernel(const int* __restrict__ idx, const float* __restrict__ emb) {
    int i = blockIdx.x * 256 + threadIdx.x;
    if (i >= Bv * Sv * Ev) return;
    int e = i % Ev;
    int m = i / Ev;
    d_text[i] = emb[idx[m] * Ev + e];
}

// ---------------- SGEMM ----------------
// BT: B is [N,K] (multiply B^T) else [K,N]
// EPI 0: plain (+bias). EPI 1: row m=b*Sv+s -> C[(s*Bv+b)*G4+n] (+bias)
// PW: scale A row m by d_pwv[m] during load (pos-weight fusion)
template <int EPI, bool BT, bool PW>
__global__ void __launch_bounds__(256, 3)
sgemm_kernel(const float* __restrict__ A, const float* __restrict__ Bm,
             const float* __restrict__ bias, float* __restrict__ C,
             int M, int N, int K) {
    __shared__ float As[8 * 128];
    __shared__ float Bs[8 * 64];
    const int m0 = blockIdx.y * 128;
    const int n0 = blockIdx.x * 64;
    const int tid = threadIdx.x;
    const int ty = tid >> 4;
    const int tx = tid & 15;

    float acc[8][4];
#pragma unroll
    for (int r = 0; r < 8; r++)
#pragma unroll
        for (int c = 0; c < 4; c++) acc[r][c] = 0.f;

    const int a_m = tid >> 1;
    const int a_k = (tid & 1) * 4;
    float pwscale = 1.f;
    if (PW) pwscale = d_pwv[m0 + a_m];

    for (int k0 = 0; k0 < K; k0 += 8) {
        float4 av = make_float4(0.f, 0.f, 0.f, 0.f);
        if (k0 + a_k < K)
            av = *(const float4*)&A[(size_t)(m0 + a_m) * K + k0 + a_k];
        if (PW) { av.x *= pwscale; av.y *= pwscale; av.z *= pwscale; av.w *= pwscale; }
        As[(a_k + 0) * 128 + a_m] = av.x;
        As[(a_k + 1) * 128 + a_m] = av.y;
        As[(a_k + 2) * 128 + a_m] = av.z;
        As[(a_k + 3) * 128 + a_m] = av.w;

        if (BT) {
            int n_l = tid >> 2;
            int kk = (tid & 3) * 2;
            int row = n0 + n_l;
#pragma unroll
            for (int d2 = 0; d2 < 2; d2++) {
                int k = k0 + kk + d2;
                Bs[(kk + d2) * 64 + n_l] = (row < N && k < K) ? Bm[(size_t)row * K + k] : 0.f;
            }
        } else {
            int kk = tid >> 5;
            int n_l = (tid & 31) * 2;
#pragma unroll
            for (int d2 = 0; d2 < 2; d2++) {
                int n = n_l + d2;
                Bs[kk * 64 + n] =
                    (k0 + kk < K && n0 + n < N) ? Bm[(size_t)(k0 + kk) * N + n0 + n] : 0.f;
            }
        }
        __syncthreads();

#pragma unroll
        for (int kk = 0; kk < 8; kk++) {
            float4 a0 = *(float4*)&As[kk * 128 + ty * 8];
            float4 a1 = *(float4*)&As[kk * 128 + ty * 8 + 4];
            float4 bv = *(float4*)&Bs[kk * 64 + tx * 4];
            float ar[8] = {a0.x, a0.y, a0.z, a0.w, a1.x, a1.y, a1.z, a1.w};
            float bc[4] = {bv.x, bv.y, bv.z, bv.w};
#pragma unroll
            for (int r = 0; r < 8; r++)
#pragma unroll
                for (int c = 0; c < 4; c++) acc[r][c] += ar[r] * bc[c];
        }
        __syncthreads();
    }

#pragma unroll
    for (int r = 0; r < 8; r++) {
        int row = m0 + ty * 8 + r;
#pragma unroll
        for (int c = 0; c < 4; c++) {
            int col = n0 + tx * 4 + c;
            if (col < N) {
                float v = acc[r][c];
                if (EPI == 0) {
                    if (bias) v += bias[col];
                    C[(size_t)row * N + col] = v;
                } else {
                    int bb = row >> 8;
                    int ss = row & 255;
                    C[(size_t)(ss * Bv + bb) * G4 + col] = v + bias[col];
                }
            }
        }
    }
}

// ---------------- persistent BiLSTM: smem-staged h, register X prefetch ----------------
__global__ void __launch_bounds__(LSTM_THREADS, 1)
lstm_persist(const float* __restrict__ Wfh, const float* __restrict__ Wbh) {
    extern __shared__ float sm[];
    float* sH = sm + SH_OFF;   // [k][b] 300x64
    float* sW = sm + SW_OFF;   // [k][jl] 300x20
    float* sG = sm + SG_OFF;   // [jl][b]
    float* sC = sm + SC_OFF;   // [u][b]

    const int d = blockIdx.x / LSTM_BLOCKS_PER_DIR;
    const int ub5 = (blockIdx.x % LSTM_BLOCKS_PER_DIR) * 5;
    const float* __restrict__ W = (d == 0) ? Wfh : Wbh;
    const int tid = threadIdx.x;

    for (int idx = tid; idx < 20 * 300; idx += LSTM_THREADS) {
        int jl = idx / 300, k = idx % 300;
        int j = (jl / 5) * 300 + ub5 + (jl % 5);
        sW[k * 20 + jl] = W[j * 300 + k];
    }
    sC[tid] = 0.f;   // tid < 320 == 5*64
    __syncthreads();

    const int jl = tid % 20;
    const int bq = tid / 20;        // 0..15
    const int b0 = bq * 4;
    const int j = (jl / 5) * 300 + ub5 + (jl % 5);
    const int u_l = tid >> 6;       // 0..4
    const int b_f = tid & 63;
    const unsigned nblk = (unsigned)LSTM_BLOCKS_PER_DIR;

    // prefetch X for step 0
    float px0, px1, px2, px3;
    {
        const int t0 = (d == 0) ? 0 : (Sv - 1);
        const float* __restrict__ Xb = d_Xg + (size_t)(d * Sv + t0) * Bv * G4;
        px0 = Xb[(b0 + 0) * G4 + j];
        px1 = Xb[(b0 + 1) * G4 + j];
        px2 = Xb[(b0 + 2) * G4 + j];
        px3 = Xb[(b0 + 3) * G4 + j];
    }

    for (int step = 0; step < Sv; step++) {
        const int t_x = (d == 0) ? step : (Sv - 1 - step);

        float acc0 = px0, acc1 = px1, acc2 = px2, acc3 = px3;

        if (step > 0) {
            const int t_hp = (d == 0) ? (step - 1) : (Sv - step);
            // cooperative copy of h_prev (contiguous 300*64 floats) into smem
            const float4* __restrict__ Hp =
                (const float4*)(d_hseq + (size_t)(d * Sv + t_hp) * Hv * Bv);
            float4* sH4 = (float4*)sH;
#pragma unroll
            for (int i = 0; i < 15; i++) sH4[tid + i * LSTM_THREADS] = Hp[tid + i * LSTM_THREADS];
            __syncthreads();

#pragma unroll 6
            for (int k = 0; k < 300; k++) {
                float w = sW[k * 20 + jl];
                float4 h4 = *(const float4*)&sH[k * 64 + b0];
                acc0 += w * h4.x;
                acc1 += w * h4.y;
                acc2 += w * h4.z;
                acc3 += w * h4.w;
            }
        }
        sG[jl * 64 + b0 + 0] = acc0;
        sG[jl * 64 + b0 + 1] = acc1;
        sG[jl * 64 + b0 + 2] = acc2;
        sG[jl * 64 + b0 + 3] = acc3;
        __syncthreads();

        // finalize: 5 units x 64 batches
        {
            float gi = sG[(0 * 5 + u_l) * 64 + b_f];
            float gf = sG[(1 * 5 + u_l) * 64 + b_f];
            float gg = sG[(2 * 5 + u_l) * 64 + b_f];
            float go = sG[(3 * 5 + u_l) * 64 + b_f];
            float cp = sC[u_l * 64 + b_f];
            float si = 1.f / (1.f + expf(-gi));
            float sf = 1.f / (1.f + expf(-gf));
            float so = 1.f / (1.f + expf(-go));
            float c = sf * cp + si * tanhf(gg);
            sC[u_l * 64 + b_f] = c;
            float h = so * tanhf(c);
            d_hseq[((size_t)(d * Sv + t_x) * Hv + ub5 + u_l) * 64 + b_f] = h;
        }

        // prefetch X for step+1 (hides latency under the barrier)
        if (step + 1 < Sv) {
            const int tn = (d == 0) ? (step + 1) : (Sv - 2 - step);
            const float* __restrict__ Xn = d_Xg + (size_t)(d * Sv + tn) * Bv * G4;
            px0 = Xn[(b0 + 0) * G4 + j];
            px1 = Xn[(b0 + 1) * G4 + j];
            px2 = Xn[(b0 + 2) * G4 + j];
            px3 = Xn[(b0 + 3) * G4 + j];
        }

        // grid barrier over this direction's blocks
        __syncthreads();
        if (tid == 0) {
            __threadfence();
            atomicAdd(&d_barr[d * Sv + step], 1u);
        }
        const unsigned* ctr = &d_barr[d * Sv + step];
        while (ld_acquire(ctr) < nblk) {}
    }
}

// ---------------- assemble text_out [b][s][600] ----------------
__global__ void assemble_to() {
    int i = blockIdx.x * 256 + threadIdx.x;
    if (i >= Bv * Sv * H2) return;
    int h = i % H2;
    int bs = i / H2;
    int s = bs % Sv;
    int b = bs / Sv;
    int dsel = (h >= Hv) ? 1 : 0;
    int u = h - dsel * Hv;
    d_to[i] = d_hseq[((size_t)(dsel * Sv + s) * Hv + u) * 64 + b];
}

// ---------------- V = bil_W @ rel_embed^T ----------------
__global__ void vprep(const float* __restrict__ bw, const float* __restrict__ re) {
    int r = blockIdx.x;
    for (int i = threadIdx.x; i < G4; i += 256) {
        float a = 0.f;
#pragma unroll
        for (int jj = 0; jj < RELDv; jj++) a += bw[i * RELDv + jj] * re[r * RELDv + jj];
        d_V[r * G4 + i] = a;
    }
}

// ---------------- relation scores ----------------
__global__ void relscore(const int* __restrict__ head, const int* __restrict__ behead,
                         const int* __restrict__ rel, const float* __restrict__ bilb) {
    int g = blockIdx.x * 8 + (threadIdx.x >> 5);
    int lane = threadIdx.x & 31;
    if (g >= Bv * Rv) return;
    int b = g / Rv;
    int rr = rel[g];
    float dotv = 0.f;
    if (rr != 0) {
        int h1 = head[g], h2 = behead[g];
        const float* __restrict__ n1 = d_to + (size_t)(b * Sv + h1) * H2;
        const float* __restrict__ n2 = d_to + (size_t)(b * Sv + h2) * H2;
        const float* __restrict__ V = d_V + rr * G4;
        for (int i = lane; i < H2; i += 32) dotv += n1[i] * V[i] + n2[i] * V[H2 + i];
    }
#pragma unroll
    for (int o = 16; o; o >>= 1) dotv += __shfl_down_sync(0xffffffffu, dotv, o);
    if (lane == 0) d_score[g] = 1.f / (1.f + expf(-(dotv + bilb[0])));
}

// ---------------- position weights ----------------
__global__ void pwv_kernel() {
    int b = blockIdx.x;
    int s = threadIdx.x;
    float tl = (float)d_tlen[b];
    float al = (float)d_alen[b];
    float l0 = (float)d_llen[b];
    float l1 = l0 + al - 1.f;
    float ctx = tl - al;
    float jf = (float)s;
    float w;
    if (jf < l0) w = 1.f - (l0 - jf) / ctx;
    else if (jf <= l1) w = 0.f;
    else if (jf < tl) w = 1.f - (jf - l1) / ctx;
    else w = 0.f;
    d_pwv[b * Sv + s] = w;
}

// ---------------- sparse GCN apply ----------------
__global__ void gcn_apply(const int* __restrict__ head, const int* __restrict__ behead,
                          const float* __restrict__ bias, float* __restrict__ out) {
    int bs = blockIdx.x;
    int b = bs >> 8;
    int s1 = bs & 255;
    const int* hd = head + b * Rv;
    int L = 0, Rr = Rv;
    while (L < Rr) { int m = (L + Rr) >> 1; if (hd[m] < s1) L = m + 1; else Rr = m; }
    int lo = L;
    Rr = Rv;
    while (L < Rr) { int m = (L + Rr) >> 1; if (hd[m] <= s1) L = m + 1; else Rr = m; }
    int hi = L;
    float den = 1.f;
    for (int r = lo; r < hi; r++) den += d_score[b * Rv + r];
    float inv = 1.f / den;
    for (int h = threadIdx.x; h < H2; h += 128) {
        float a = 0.f;
        for (int r = lo; r < hi; r++)
            a += d_score[b * Rv + r] * d_hid[(size_t)(b * Sv + behead[b * Rv + r]) * H2 + h];
        float v = a * inv + bias[h];
        out[(size_t)(b * Sv + s1) * H2 + h] = fmaxf(v, 0.f);
    }
}

// ---------------- attention ----------------
__global__ void xsum_kernel(const float* __restrict__ x) {
    int b = blockIdx.x;
    int h = threadIdx.x;
    if (h >= H2) return;
    int l0 = d_llen[b];
    int l1 = l0 + d_alen[b] - 1;
    if (l1 > Sv - 1) l1 = Sv - 1;
    float a = 0.f;
    for (int s = l0; s <= l1; s++) a += x[(size_t)(b * Sv + s) * H2 + h];
    d_xsum[b * H2 + h] = a;
}

__global__ void attscore() {
    int g = blockIdx.x * 8 + (threadIdx.x >> 5);
    int lane = threadIdx.x & 31;
    if (g >= Bv * Sv) return;
    int b = g >> 8;
    float a = 0.f;
    for (int i = lane; i < H2; i += 32) a += d_xsum[b * H2 + i] * d_to[(size_t)g * H2 + i];
#pragma unroll
    for (int o = 16; o; o >>= 1) a += __shfl_down_sync(0xffffffffu, a, o);
    if (lane == 0) d_attsc[g] = a;
}

__global__ void softmax_kernel() {
    __shared__ float red[256];
    int b = blockIdx.x;
    int tid = threadIdx.x;
    float v = d_attsc[b * Sv + tid];
    red[tid] = v;
    __syncthreads();
    for (int o = 128; o; o >>= 1) {
        if (tid < o) red[tid] = fmaxf(red[tid], red[tid + o]);
        __syncthreads();
    }
    float smax = red[0];
    __syncthreads();
    float e = expf(v - smax);
    red[tid] = e;
    __syncthreads();
    for (int o = 128; o; o >>= 1) {
        if (tid < o) red[tid] += red[tid + o];
        __syncthreads();
    }
    d_alpha[b * Sv + tid] = e / red[0];
}

__global__ void outvec_kernel() {
    int b = blockIdx.x;
    int h = threadIdx.x;
    if (h >= H2) return;
    float a = 0.f;
    for (int s = 0; s < Sv; s++) a += d_alpha[b * Sv + s] * d_to[(size_t)(b * Sv + s) * H2 + h];
    d_ov[b * H2 + h] = a;
}

__global__ void final_fc(const float* __restrict__ fcW, const float* __restrict__ fcb,
                         float* __restrict__ out) {
    int b = blockIdx.x;
    int p = threadIdx.x >> 5;
    int lane = threadIdx.x & 31;
    if (p >= 3) return;
    float a = 0.f;
    for (int h = lane; h < H2; h += 32) a += d_ov[b * H2 + h] * fcW[h * 3 + p];
#pragma unroll
    for (int o = 16; o; o >>= 1) a += __shfl_down_sync(0xffffffffu, a, o);
    if (lane == 0) out[b * 3 + p] = a + fcb[p];
}

// ---------------- launch ----------------
extern "C" void kernel_launch(void* const* d_in, const int* in_sizes, int n_in,
                              void* d_out, int out_size) {
    const int* text_indices = (const int*)d_in[0];
    const int* aspect_indices = (const int*)d_in[1];
    const int* left_indices = (const int*)d_in[2];
    // d_in[3] = adj (dense) — unused
    const int* head_vector = (const int*)d_in[4];
    const int* behead_vector = (const int*)d_in[5];
    const int* relation_vector = (const int*)d_in[6];
    const float* embed_table = (const float*)d_in[7];
    const float* rel_embed = (const float*)d_in[8];
    const float* Wf_ih = (const float*)d_in[9];
    const float* Wf_hh = (const float*)d_in[10];
    const float* bf = (const float*)d_in[11];
    const float* Wb_ih = (const float*)d_in[12];
    const float* Wb_hh = (const float*)d_in[13];
    const float* bb = (const float*)d_in[14];
    const float* bil_W = (const float*)d_in[15];
    const float* bil_b = (const float*)d_in[16];
    const float* gc1_W = (const float*)d_in[17];
    const float* gc1_b = (const float*)d_in[18];
    const float* gc2_W = (const float*)d_in[19];
    const float* gc2_b = (const float*)d_in[20];
    const float* fc_W = (const float*)d_in[21];
    const float* fc_b = (const float*)d_in[22];
    float* out = (float*)d_out;

    float* p_text;  cudaGetSymbolAddress((void**)&p_text, d_text);
    float* p_Xg;    cudaGetSymbolAddress((void**)&p_Xg, d_Xg);
    float* p_to;    cudaGetSymbolAddress((void**)&p_to, d_to);
    float* p_hid;   cudaGetSymbolAddress((void**)&p_hid, d_hid);
    float* p_x1;    cudaGetSymbolAddress((void**)&p_x1, d_x1);

    cudaFuncSetAttribute(lstm_persist, cudaFuncAttributeMaxDynamicSharedMemorySize,
                         LSTM_SMEM_BYTES);

    len_kernel<<<1, 64>>>(text_indices, aspect_indices, left_indices);
    embed_kernel<<<(Bv * Sv * Ev + 255) / 256, 256>>>(text_indices, embed_table);

    {
        dim3 g((G4 + 63) / 64, (Bv * Sv) / 128);
        sgemm_kernel<1, true, false><<<g, 256>>>(p_text, Wf_ih, bf, p_Xg, Bv * Sv, G4, Ev);
        sgemm_kernel<1, true, false><<<g, 256>>>(p_text, Wb_ih, bb,
                                                 p_Xg + (size_t)Sv * Bv * G4, Bv * Sv, G4, Ev);
    }

    barr_reset<<<1, 512>>>();
    lstm_persist<<<2 * LSTM_BLOCKS_PER_DIR, LSTM_THREADS, LSTM_SMEM_BYTES>>>(Wf_hh, Wb_hh);

    assemble_to<<<(Bv * Sv * H2 + 255) / 256, 256>>>();

    vprep<<<NRELv, 256>>>(bil_W, rel_embed);
    relscore<<<(Bv * Rv) / 8, 256>>>(head_vector, behead_vector, relation_vector, bil_b);

    pwv_kernel<<<Bv, Sv>>>();

    // GCN layer 1 (pos-weight fused into A-load)
    {
        dim3 g((H2 + 63) / 64, (Bv * Sv) / 128);
        sgemm_kernel<0, false, true><<<g, 256>>>(p_to, gc1_W, nullptr, p_hid, Bv * Sv, H2, H2);
    }
    gcn_apply<<<Bv * Sv, 128>>>(head_vector, behead_vector, gc1_b, p_x1);

    // GCN layer 2
    {
        dim3 g((H2 + 63) / 64, (Bv * Sv) / 128);
        sgemm_kernel<0, false, true><<<g, 256>>>(p_x1, gc2_W, nullptr, p_hid, Bv * Sv, H2, H2);
    }
    gcn_apply<<<Bv * Sv, 128>>>(head_vector, behead_vector, gc2_b, p_x1);

    xsum_kernel<<<Bv, 640>>>(p_x1);
    attscore<<<(Bv * Sv) / 8, 256>>>();
    softmax_kernel<<<Bv, 256>>>();
    outvec_kernel<<<Bv, 640>>>();
    final_fc<<<Bv, 96>>>(fc_W, fc_b, out);

    (void)in_sizes; (void)n_in; (void)out_size;
}

// round 7
// speedup vs baseline: 2.5566x; 1.2699x over previous
#include <cuda_runtime.h>
#include <stdint.h>
#include <math.h>

#define Bv 64
#define Sv 256
#define Ev 300
#define Hv 300
#define H2 600
#define G4 1200
#define Rv 512
#define NRELv 46
#define RELDv 50

#define LSTM_BLOCKS_PER_DIR 60
#define LSTM_THREADS 320

#define SH_OFF 0
#define SW_OFF 19200
#define SG_OFF (19200 + 6000)
#define SC_OFF (SG_OFF + 1280)
#define LSTM_SMEM_BYTES ((SC_OFF + 320) * 4)

// mma gemm tile config
#define ASTR 136   // As row stride (floats): banks (8*tig+grp) distinct
#define BSTR 72    // Bs row stride

// ---------------- device scratch ----------------
__device__ float d_text[Bv * Sv * Ev];
__device__ float d_Xg[2 * Sv * Bv * G4];
__device__ float d_hseq[2 * Sv * Hv * Bv];
__device__ float d_to[Bv * Sv * H2];
__device__ float d_hid[Bv * Sv * H2];
__device__ float d_x1[Bv * Sv * H2];
__device__ float d_V[NRELv * G4];
__device__ float d_score[Bv * Rv];
__device__ float d_pwv[Bv * Sv];
__device__ float d_xsum[Bv * H2];
__device__ float d_attsc[Bv * Sv];
__device__ float d_alpha[Bv * Sv];
__device__ float d_ov[Bv * H2];
__device__ int d_tlen[Bv], d_alen[Bv], d_llen[Bv];
__device__ unsigned d_barr[2 * Sv];

__device__ __forceinline__ unsigned ld_acquire(const unsigned* p) {
    unsigned v;
    asm volatile("ld.acquire.gpu.global.u32 %0, [%1];" : "=r"(v) : "l"(p) : "memory");
    return v;
}

__device__ __forceinline__ float to_tf32(float x) {
    uint32_t r;
    asm("cvt.rna.tf32.f32 %0, %1;" : "=r"(r) : "f"(x));
    return __uint_as_float(r);
}

// ---------------- barrier reset ----------------
__global__ void barr_reset() {
    int i = threadIdx.x;
    if (i < 2 * Sv) d_barr[i] = 0u;
}

// ---------------- lengths ----------------
__global__ void len_kernel(const int* __restrict__ ti, const int* __restrict__ ai,
                           const int* __restrict__ li) {
    int b = threadIdx.x;
    if (b >= Bv) return;
    int t = 0;
    for (int s = 0; s < Sv; s++) t += (ti[b * Sv + s] != 0);
    int a = 0;
    for (int s = 0; s < 4; s++) a += (ai[b * 4 + s] != 0);
    int l = 0;
    for (int s = 0; s < 64; s++) l += (li[b * 64 + s] != 0);
    d_tlen[b] = t;
    d_alen[b] = a;
    d_llen[b] = l;
}

// ---------------- embedding gather ----------------
__global__ void embed_kernel(const int* __restrict__ idx, const float* __restrict__ emb) {
    int i = blockIdx.x * 256 + threadIdx.x;
    if (i >= Bv * Sv * Ev) return;
    int e = i % Ev;
    int m = i / Ev;
    d_text[i] = emb[idx[m] * Ev + e];
}

// ---------------- tf32 MMA GEMM: C[M,N] = A[M,K] * B (+bias) ----------------
// BT: B is [N,K] row-major (use B^T). else B is [K,N].
// EPI 0: C[m*N+n] (+bias if non-null)
// EPI 1: row m=b*Sv+s -> C[(s*Bv+b)*G4+n] = acc + bias[n]
// PW: scale A row m by d_pwv[m] on load.
// Block 256 thr (8 warps), tile 128x64, k-step 16.
template <int EPI, bool BT, bool PW>
__global__ void __launch_bounds__(256, 3)
mma_gemm(const float* __restrict__ A, const float* __restrict__ Bm,
         const float* __restrict__ bias, float* __restrict__ C,
         int M, int N, int K) {
    __shared__ float As[16 * ASTR];
    __shared__ float Bs[16 * BSTR];

    const int m0 = blockIdx.y * 128;
    const int n0 = blockIdx.x * 64;
    const int tid = threadIdx.x;
    const int wid = tid >> 5;
    const int lane = tid & 31;
    const int grp = lane >> 2;      // 0..7
    const int tig = lane & 3;       // 0..3
    const int m_base = wid * 16;

    float c[8][4];
#pragma unroll
    for (int n = 0; n < 8; n++)
#pragma unroll
        for (int i = 0; i < 4; i++) c[n][i] = 0.f;

    const int a_m = tid >> 1;          // 0..127
    const int a_k4 = (tid & 1) * 4;    // 0 or 4
    float pwscale = 1.f;
    if (PW) pwscale = d_pwv[m0 + a_m];

    const int kend = (K + 15) & ~15;

    for (int k0 = 0; k0 < kend; k0 += 16) {
        // ---- load A tile (128 x 16) -> As[k][m], tf32 ----
#pragma unroll
        for (int kk2 = 0; kk2 < 16; kk2 += 8) {
            int k = k0 + kk2 + a_k4;
            float4 av = make_float4(0.f, 0.f, 0.f, 0.f);
            if (k < K) av = *(const float4*)&A[(size_t)(m0 + a_m) * K + k];
            if (PW) { av.x *= pwscale; av.y *= pwscale; av.z *= pwscale; av.w *= pwscale; }
            As[(kk2 + a_k4 + 0) * ASTR + a_m] = to_tf32(av.x);
            As[(kk2 + a_k4 + 1) * ASTR + a_m] = to_tf32(av.y);
            As[(kk2 + a_k4 + 2) * ASTR + a_m] = to_tf32(av.z);
            As[(kk2 + a_k4 + 3) * ASTR + a_m] = to_tf32(av.w);
        }
        // ---- load B tile -> Bs[k][n], tf32 ----
        if (BT) {
            int n_l = tid >> 2;            // 0..63
            int kk = (tid & 3) * 4;        // 0,4,8,12
            int row = n0 + n_l;
            int k = k0 + kk;
            float4 bv = make_float4(0.f, 0.f, 0.f, 0.f);
            if (row < N && k < K) bv = *(const float4*)&Bm[(size_t)row * K + k];
            Bs[(kk + 0) * BSTR + n_l] = to_tf32(bv.x);
            Bs[(kk + 1) * BSTR + n_l] = to_tf32(bv.y);
            Bs[(kk + 2) * BSTR + n_l] = to_tf32(bv.z);
            Bs[(kk + 3) * BSTR + n_l] = to_tf32(bv.w);
        } else {
            int kk = tid >> 4;             // 0..15
            int n_l = (tid & 15) * 4;      // 0..60
            int k = k0 + kk;
#pragma unroll
            for (int i = 0; i < 4; i++) {
                int n = n0 + n_l + i;
                float v = (k < K && n < N) ? Bm[(size_t)k * N + n] : 0.f;
                Bs[kk * BSTR + n_l + i] = to_tf32(v);
            }
        }
        __syncthreads();

        // ---- mma: warp computes 16 x 64 strip ----
#pragma unroll
        for (int ksub = 0; ksub < 2; ksub++) {
            const int kb = ksub * 8;
            uint32_t a0 = __float_as_uint(As[(kb + tig) * ASTR + m_base + grp]);
            uint32_t a1 = __float_as_uint(As[(kb + tig) * ASTR + m_base + grp + 8]);
            uint32_t a2 = __float_as_uint(As[(kb + tig + 4) * ASTR + m_base + grp]);
            uint32_t a3 = __float_as_uint(As[(kb + tig + 4) * ASTR + m_base + grp + 8]);
#pragma unroll
            for (int n = 0; n < 8; n++) {
                uint32_t b0 = __float_as_uint(Bs[(kb + tig) * BSTR + n * 8 + grp]);
                uint32_t b1 = __float_as_uint(Bs[(kb + tig + 4) * BSTR + n * 8 + grp]);
                asm volatile(
                    "mma.sync.aligned.m16n8k8.row.col.f32.tf32.tf32.f32 "
                    "{%0,%1,%2,%3}, {%4,%5,%6,%7}, {%8,%9}, {%0,%1,%2,%3};"
                    : "+f"(c[n][0]), "+f"(c[n][1]), "+f"(c[n][2]), "+f"(c[n][3])
                    : "r"(a0), "r"(a1), "r"(a2), "r"(a3), "r"(b0), "r"(b1));
            }
        }
        __syncthreads();
    }

    // ---- epilogue ----
#pragma unroll
    for (int n = 0; n < 8; n++) {
        int col0 = n0 + n * 8 + 2 * tig;
#pragma unroll
        for (int half = 0; half < 2; half++) {
            int row = m0 + m_base + grp + half * 8;
            float v0 = c[n][half * 2 + 0];
            float v1 = c[n][half * 2 + 1];
            if (EPI == 0) {
                float b0 = bias ? bias[col0] : 0.f;
                float b1 = (bias && col0 + 1 < N) ? bias[col0 + 1] : 0.f;
                if (col0 < N) C[(size_t)row * N + col0] = v0 + b0;
                if (col0 + 1 < N) C[(size_t)row * N + col0 + 1] = v1 + b1;
            } else {
                int bb = row >> 8;
                int ss = row & 255;
                size_t base = (size_t)(ss * Bv + bb) * G4;
                if (col0 < N) C[base + col0] = v0 + bias[col0];
                if (col0 + 1 < N) C[base + col0 + 1] = v1 + bias[col0 + 1];
            }
        }
    }
}

// ---------------- persistent BiLSTM ----------------
__global__ void __launch_bounds__(LSTM_THREADS, 1)
lstm_persist(const float* __restrict__ Wfh, const float* __restrict__ Wbh) {
    extern __shared__ float sm[];
    float* sH = sm + SH_OFF;
    float* sW = sm + SW_OFF;
    float* sG = sm + SG_OFF;
    float* sC = sm + SC_OFF;

    const int d = blockIdx.x / LSTM_BLOCKS_PER_DIR;
    const int ub5 = (blockIdx.x % LSTM_BLOCKS_PER_DIR) * 5;
    const float* __restrict__ W = (d == 0) ? Wfh : Wbh;
    const int tid = threadIdx.x;

    for (int idx = tid; idx < 20 * 300; idx += LSTM_THREADS) {
        int jl = idx / 300, k = idx % 300;
        int j = (jl / 5) * 300 + ub5 + (jl % 5);
        sW[k * 20 + jl] = W[j * 300 + k];
    }
    sC[tid] = 0.f;
    __syncthreads();

    const int jl = tid % 20;
    const int bq = tid / 20;
    const int b0 = bq * 4;
    const int j = (jl / 5) * 300 + ub5 + (jl % 5);
    const int u_l = tid >> 6;
    const int b_f = tid & 63;
    const unsigned nblk = (unsigned)LSTM_BLOCKS_PER_DIR;

    float px0, px1, px2, px3;
    {
        const int t0 = (d == 0) ? 0 : (Sv - 1);
        const float* __restrict__ Xb = d_Xg + (size_t)(d * Sv + t0) * Bv * G4;
        px0 = Xb[(b0 + 0) * G4 + j];
        px1 = Xb[(b0 + 1) * G4 + j];
        px2 = Xb[(b0 + 2) * G4 + j];
        px3 = Xb[(b0 + 3) * G4 + j];
    }

    for (int step = 0; step < Sv; step++) {
        const int t_x = (d == 0) ? step : (Sv - 1 - step);

        float acc0 = px0, acc1 = px1, acc2 = px2, acc3 = px3;

        if (step > 0) {
            const int t_hp = (d == 0) ? (step - 1) : (Sv - step);
            const float4* __restrict__ Hp =
                (const float4*)(d_hseq + (size_t)(d * Sv + t_hp) * Hv * Bv);
            float4* sH4 = (float4*)sH;
#pragma unroll
            for (int i = 0; i < 15; i++) sH4[tid + i * LSTM_THREADS] = Hp[tid + i * LSTM_THREADS];
            __syncthreads();

#pragma unroll 6
            for (int k = 0; k < 300; k++) {
                float w = sW[k * 20 + jl];
                float4 h4 = *(const float4*)&sH[k * 64 + b0];
                acc0 += w * h4.x;
                acc1 += w * h4.y;
                acc2 += w * h4.z;
                acc3 += w * h4.w;
            }
        }
        sG[jl * 64 + b0 + 0] = acc0;
        sG[jl * 64 + b0 + 1] = acc1;
        sG[jl * 64 + b0 + 2] = acc2;
        sG[jl * 64 + b0 + 3] = acc3;
        __syncthreads();

        {
            float gi = sG[(0 * 5 + u_l) * 64 + b_f];
            float gf = sG[(1 * 5 + u_l) * 64 + b_f];
            float gg = sG[(2 * 5 + u_l) * 64 + b_f];
            float go = sG[(3 * 5 + u_l) * 64 + b_f];
            float cp = sC[u_l * 64 + b_f];
            float si = 1.f / (1.f + expf(-gi));
            float sf = 1.f / (1.f + expf(-gf));
            float so = 1.f / (1.f + expf(-go));
            float cc = sf * cp + si * tanhf(gg);
            sC[u_l * 64 + b_f] = cc;
            float h = so * tanhf(cc);
            d_hseq[((size_t)(d * Sv + t_x) * Hv + ub5 + u_l) * 64 + b_f] = h;
        }

        if (step + 1 < Sv) {
            const int tn = (d == 0) ? (step + 1) : (Sv - 2 - step);
            const float* __restrict__ Xn = d_Xg + (size_t)(d * Sv + tn) * Bv * G4;
            px0 = Xn[(b0 + 0) * G4 + j];
            px1 = Xn[(b0 + 1) * G4 + j];
            px2 = Xn[(b0 + 2) * G4 + j];
            px3 = Xn[(b0 + 3) * G4 + j];
        }

        __syncthreads();
        if (tid == 0) {
            __threadfence();
            atomicAdd(&d_barr[d * Sv + step], 1u);
        }
        const unsigned* ctr = &d_barr[d * Sv + step];
        while (ld_acquire(ctr) < nblk) {}
    }
}

// ---------------- assemble text_out ----------------
__global__ void assemble_to() {
    int i = blockIdx.x * 256 + threadIdx.x;
    if (i >= Bv * Sv * H2) return;
    int h = i % H2;
    int bs = i / H2;
    int s = bs % Sv;
    int b = bs / Sv;
    int dsel = (h >= Hv) ? 1 : 0;
    int u = h - dsel * Hv;
    d_to[i] = d_hseq[((size_t)(dsel * Sv + s) * Hv + u) * 64 + b];
}

// ---------------- V = bil_W @ rel_embed^T ----------------
__global__ void vprep(const float* __restrict__ bw, const float* __restrict__ re) {
    int r = blockIdx.x;
    for (int i = threadIdx.x; i < G4; i += 256) {
        float a = 0.f;
#pragma unroll
        for (int jj = 0; jj < RELDv; jj++) a += bw[i * RELDv + jj] * re[r * RELDv + jj];
        d_V[r * G4 + i] = a;
    }
}

// ---------------- relation scores ----------------
__global__ void relscore(const int* __restrict__ head, const int* __restrict__ behead,
                         const int* __restrict__ rel, const float* __restrict__ bilb) {
    int g = blockIdx.x * 8 + (threadIdx.x >> 5);
    int lane = threadIdx.x & 31;
    if (g >= Bv * Rv) return;
    int b = g / Rv;
    int rr = rel[g];
    float dotv = 0.f;
    if (rr != 0) {
        int h1 = head[g], h2 = behead[g];
        const float* __restrict__ n1 = d_to + (size_t)(b * Sv + h1) * H2;
        const float* __restrict__ n2 = d_to + (size_t)(b * Sv + h2) * H2;
        const float* __restrict__ V = d_V + rr * G4;
        for (int i = lane; i < H2; i += 32) dotv += n1[i] * V[i] + n2[i] * V[H2 + i];
    }
#pragma unroll
    for (int o = 16; o; o >>= 1) dotv += __shfl_down_sync(0xffffffffu, dotv, o);
    if (lane == 0) d_score[g] = 1.f / (1.f + expf(-(dotv + bilb[0])));
}

// ---------------- position weights ----------------
__global__ void pwv_kernel() {
    int b = blockIdx.x;
    int s = threadIdx.x;
    float tl = (float)d_tlen[b];
    float al = (float)d_alen[b];
    float l0 = (float)d_llen[b];
    float l1 = l0 + al - 1.f;
    float ctx = tl - al;
    float jf = (float)s;
    float w;
    if (jf < l0) w = 1.f - (l0 - jf) / ctx;
    else if (jf <= l1) w = 0.f;
    else if (jf < tl) w = 1.f - (jf - l1) / ctx;
    else w = 0.f;
    d_pwv[b * Sv + s] = w;
}

// ---------------- sparse GCN apply ----------------
__global__ void gcn_apply(const int* __restrict__ head, const int* __restrict__ behead,
                          const float* __restrict__ bias, float* __restrict__ out) {
    int bs = blockIdx.x;
    int b = bs >> 8;
    int s1 = bs & 255;
    const int* hd = head + b * Rv;
    int L = 0, Rr = Rv;
    while (L < Rr) { int m = (L + Rr) >> 1; if (hd[m] < s1) L = m + 1; else Rr = m; }
    int lo = L;
    Rr = Rv;
    while (L < Rr) { int m = (L + Rr) >> 1; if (hd[m] <= s1) L = m + 1; else Rr = m; }
    int hi = L;
    float den = 1.f;
    for (int r = lo; r < hi; r++) den += d_score[b * Rv + r];
    float inv = 1.f / den;
    for (int h = threadIdx.x; h < H2; h += 128) {
        float a = 0.f;
        for (int r = lo; r < hi; r++)
            a += d_score[b * Rv + r] * d_hid[(size_t)(b * Sv + behead[b * Rv + r]) * H2 + h];
        float v = a * inv + bias[h];
        out[(size_t)(b * Sv + s1) * H2 + h] = fmaxf(v, 0.f);
    }
}

// ---------------- attention ----------------
__global__ void xsum_kernel(const float* __restrict__ x) {
    int b = blockIdx.x;
    int h = threadIdx.x;
    if (h >= H2) return;
    int l0 = d_llen[b];
    int l1 = l0 + d_alen[b] - 1;
    if (l1 > Sv - 1) l1 = Sv - 1;
    float a = 0.f;
    for (int s = l0; s <= l1; s++) a += x[(size_t)(b * Sv + s) * H2 + h];
    d_xsum[b * H2 + h] = a;
}

__global__ void attscore() {
    int g = blockIdx.x * 8 + (threadIdx.x >> 5);
    int lane = threadIdx.x & 31;
    if (g >= Bv * Sv) return;
    int b = g >> 8;
    float a = 0.f;
    for (int i = lane; i < H2; i += 32) a += d_xsum[b * H2 + i] * d_to[(size_t)g * H2 + i];
#pragma unroll
    for (int o = 16; o; o >>= 1) a += __shfl_down_sync(0xffffffffu, a, o);
    if (lane == 0) d_attsc[g] = a;
}

__global__ void softmax_kernel() {
    __shared__ float red[256];
    int b = blockIdx.x;
    int tid = threadIdx.x;
    float v = d_attsc[b * Sv + tid];
    red[tid] = v;
    __syncthreads();
    for (int o = 128; o; o >>= 1) {
        if (tid < o) red[tid] = fmaxf(red[tid], red[tid + o]);
        __syncthreads();
    }
    float smax = red[0];
    __syncthreads();
    float e = expf(v - smax);
    red[tid] = e;
    __syncthreads();
    for (int o = 128; o; o >>= 1) {
        if (tid < o) red[tid] += red[tid + o];
        __syncthreads();
    }
    d_alpha[b * Sv + tid] = e / red[0];
}

__global__ void outvec_kernel() {
    int b = blockIdx.x;
    int h = threadIdx.x;
    if (h >= H2) return;
    float a = 0.f;
    for (int s = 0; s < Sv; s++) a += d_alpha[b * Sv + s] * d_to[(size_t)(b * Sv + s) * H2 + h];
    d_ov[b * H2 + h] = a;
}

__global__ void final_fc(const float* __restrict__ fcW, const float* __restrict__ fcb,
                         float* __restrict__ out) {
    int b = blockIdx.x;
    int p = threadIdx.x >> 5;
    int lane = threadIdx.x & 31;
    if (p >= 3) return;
    float a = 0.f;
    for (int h = lane; h < H2; h += 32) a += d_ov[b * H2 + h] * fcW[h * 3 + p];
#pragma unroll
    for (int o = 16; o; o >>= 1) a += __shfl_down_sync(0xffffffffu, a, o);
    if (lane == 0) out[b * 3 + p] = a + fcb[p];
}

// ---------------- launch ----------------
extern "C" void kernel_launch(void* const* d_in, const int* in_sizes, int n_in,
                              void* d_out, int out_size) {
    const int* text_indices = (const int*)d_in[0];
    const int* aspect_indices = (const int*)d_in[1];
    const int* left_indices = (const int*)d_in[2];
    const int* head_vector = (const int*)d_in[4];
    const int* behead_vector = (const int*)d_in[5];
    const int* relation_vector = (const int*)d_in[6];
    const float* embed_table = (const float*)d_in[7];
    const float* rel_embed = (const float*)d_in[8];
    const float* Wf_ih = (const float*)d_in[9];
    const float* Wf_hh = (const float*)d_in[10];
    const float* bf = (const float*)d_in[11];
    const float* Wb_ih = (const float*)d_in[12];
    const float* Wb_hh = (const float*)d_in[13];
    const float* bb = (const float*)d_in[14];
    const float* bil_W = (const float*)d_in[15];
    const float* bil_b = (const float*)d_in[16];
    const float* gc1_W = (const float*)d_in[17];
    const float* gc1_b = (const float*)d_in[18];
    const float* gc2_W = (const float*)d_in[19];
    const float* gc2_b = (const float*)d_in[20];
    const float* fc_W = (const float*)d_in[21];
    const float* fc_b = (const float*)d_in[22];
    float* out = (float*)d_out;

    float* p_text;  cudaGetSymbolAddress((void**)&p_text, d_text);
    float* p_Xg;    cudaGetSymbolAddress((void**)&p_Xg, d_Xg);
    float* p_to;    cudaGetSymbolAddress((void**)&p_to, d_to);
    float* p_hid;   cudaGetSymbolAddress((void**)&p_hid, d_hid);
    float* p_x1;    cudaGetSymbolAddress((void**)&p_x1, d_x1);

    cudaFuncSetAttribute(lstm_persist, cudaFuncAttributeMaxDynamicSharedMemorySize,
                         LSTM_SMEM_BYTES);

    len_kernel<<<1, 64>>>(text_indices, aspect_indices, left_indices);
    embed_kernel<<<(Bv * Sv * Ev + 255) / 256, 256>>>(text_indices, embed_table);

    // input-side gate GEMMs (tf32 tensor cores)
    {
        dim3 g((G4 + 63) / 64, (Bv * Sv) / 128);
        mma_gemm<1, true, false><<<g, 256>>>(p_text, Wf_ih, bf, p_Xg, Bv * Sv, G4, Ev);
        mma_gemm<1, true, false><<<g, 256>>>(p_text, Wb_ih, bb,
                                             p_Xg + (size_t)Sv * Bv * G4, Bv * Sv, G4, Ev);
    }

    barr_reset<<<1, 512>>>();
    lstm_persist<<<2 * LSTM_BLOCKS_PER_DIR, LSTM_THREADS, LSTM_SMEM_BYTES>>>(Wf_hh, Wb_hh);

    assemble_to<<<(Bv * Sv * H2 + 255) / 256, 256>>>();

    vprep<<<NRELv, 256>>>(bil_W, rel_embed);
    relscore<<<(Bv * Rv) / 8, 256>>>(head_vector, behead_vector, relation_vector, bil_b);

    pwv_kernel<<<Bv, Sv>>>();

    // GCN layer 1 (pos-weight fused)
    {
        dim3 g((H2 + 63) / 64, (Bv * Sv) / 128);
        mma_gemm<0, false, true><<<g, 256>>>(p_to, gc1_W, nullptr, p_hid, Bv * Sv, H2, H2);
    }
    gcn_apply<<<Bv * Sv, 128>>>(head_vector, behead_vector, gc1_b, p_x1);

    // GCN layer 2
    {
        dim3 g((H2 + 63) / 64, (Bv * Sv) / 128);
        mma_gemm<0, false, true><<<g, 256>>>(p_x1, gc2_W, nullptr, p_hid, Bv * Sv, H2, H2);
    }
    gcn_apply<<<Bv * Sv, 128>>>(head_vector, behead_vector, gc2_b, p_x1);

    xsum_kernel<<<Bv, 640>>>(p_x1);
    attscore<<<(Bv * Sv) / 8, 256>>>();
    softmax_kernel<<<Bv, 256>>>();
    outvec_kernel<<<Bv, 640>>>();
    final_fc<<<Bv, 96>>>(fc_W, fc_b, out);

    (void)in_sizes; (void)n_in; (void)out_size;
}